// round 7
// baseline (speedup 1.0000x reference)
#include <cuda_runtime.h>
#include <cuda_bf16.h>
#include <cstdint>

#define D_MODEL 1024
#define N_HEADS 16
#define DK      64
#define B_SIZE  2
#define S_LEN   2048
#define M_ROWS  (B_SIZE * S_LEN)   // 4096
#define BHS     (B_SIZE * N_HEADS * S_LEN)

// ---------------- scratch ----------------
__device__ float g_Vh[B_SIZE * N_HEADS * S_LEN * DK];          // V head-split fp32 (pre-transpose)

__device__ __nv_bfloat16 g_Ah[3][(size_t)M_ROWS * D_MODEL];
__device__ __nv_bfloat16 g_Al[3][(size_t)M_ROWS * D_MODEL];
__device__ __nv_bfloat16 g_Oh[(size_t)M_ROWS * D_MODEL];       // attn out hi
__device__ __nv_bfloat16 g_Ol[(size_t)M_ROWS * D_MODEL];       // attn out lo
__device__ __nv_bfloat16 g_Wth[4][(size_t)D_MODEL * D_MODEL];  // W^T hi [n][k]
__device__ __nv_bfloat16 g_Wtl[4][(size_t)D_MODEL * D_MODEL];  // W^T lo [n][k]

// attention operands (bf16 split)
__device__ __nv_bfloat16 g_Qbh[(size_t)M_ROWS * D_MODEL];      // [B,H,S,DK] hi, scaled 1/8
__device__ __nv_bfloat16 g_Qbl[(size_t)M_ROWS * D_MODEL];
__device__ __nv_bfloat16 g_Kbh[(size_t)M_ROWS * D_MODEL];      // [B,H,S,DK] hi (K + kpe)
__device__ __nv_bfloat16 g_Kbl[(size_t)M_ROWS * D_MODEL];
__device__ __nv_bfloat16 g_Vth[(size_t)M_ROWS * D_MODEL];      // [B,H,DK,S] hi (transposed)
__device__ __nv_bfloat16 g_Vtl[(size_t)M_ROWS * D_MODEL];

// split-K attention partials
__device__ float  g_Opart[2][(size_t)BHS * DK];                // raw (unnormalized) O
__device__ float2 g_MLpart[2][BHS];                            // (m, l) per row

// ======================= helpers =======================
__device__ __forceinline__ uint32_t smem_u32(const void* p) {
    uint32_t a;
    asm("{ .reg .u64 t; cvta.to.shared.u64 t, %1; cvt.u32.u64 %0, t; }" : "=r"(a) : "l"(p));
    return a;
}
__device__ __forceinline__ void cp16(uint32_t dst, const void* src) {
    asm volatile("cp.async.cg.shared.global [%0], [%1], 16;" :: "r"(dst), "l"(src));
}
__device__ __forceinline__ void ldsm_x4(uint32_t& r0, uint32_t& r1, uint32_t& r2, uint32_t& r3, uint32_t addr) {
    asm volatile("ldmatrix.sync.aligned.m8n8.x4.shared.b16 {%0,%1,%2,%3}, [%4];"
        : "=r"(r0), "=r"(r1), "=r"(r2), "=r"(r3) : "r"(addr));
}
__device__ __forceinline__ void ldsm_x2(uint32_t& r0, uint32_t& r1, uint32_t addr) {
    asm volatile("ldmatrix.sync.aligned.m8n8.x2.shared.b16 {%0,%1}, [%2];"
        : "=r"(r0), "=r"(r1) : "r"(addr));
}
__device__ __forceinline__ void mma_bf16(float* c, const uint32_t* a, uint32_t b0, uint32_t b1) {
    asm volatile("mma.sync.aligned.m16n8k16.row.col.f32.bf16.bf16.f32 "
        "{%0,%1,%2,%3}, {%4,%5,%6,%7}, {%8,%9}, {%0,%1,%2,%3};"
        : "+f"(c[0]), "+f"(c[1]), "+f"(c[2]), "+f"(c[3])
        : "r"(a[0]), "r"(a[1]), "r"(a[2]), "r"(a[3]), "r"(b0), "r"(b1));
}
__device__ __forceinline__ void split1(float x, __nv_bfloat16& h, __nv_bfloat16& l) {
    h = __float2bfloat16_rn(x);
    l = __float2bfloat16_rn(x - __bfloat162float(h));
}
__device__ __forceinline__ uint32_t pack_bf(__nv_bfloat16 a, __nv_bfloat16 b) {
    __nv_bfloat162 t(a, b);
    return *(uint32_t*)&t;
}

// ======================= split prep kernels =======================
__global__ __launch_bounds__(256) void split_qkv_kernel(
    const float* __restrict__ q, const float* __restrict__ k, const float* __restrict__ v)
{
    int z = blockIdx.y;
    const float* src = (z == 0) ? q : (z == 1) ? k : v;
    __nv_bfloat16* hi = g_Ah[z];
    __nv_bfloat16* lo = g_Al[z];
    size_t i = ((size_t)blockIdx.x * 256 + threadIdx.x) * 4;
    float4 a = *(const float4*)(src + i);
    __nv_bfloat16 h0,h1,h2,h3,l0,l1,l2,l3;
    split1(a.x,h0,l0); split1(a.y,h1,l1); split1(a.z,h2,l2); split1(a.w,h3,l3);
    *(__nv_bfloat162*)(hi+i)   = __nv_bfloat162(h0,h1);
    *(__nv_bfloat162*)(hi+i+2) = __nv_bfloat162(h2,h3);
    *(__nv_bfloat162*)(lo+i)   = __nv_bfloat162(l0,l1);
    *(__nv_bfloat162*)(lo+i+2) = __nv_bfloat162(l2,l3);
}

__global__ void splitW_kernel(
    const float* __restrict__ Wq, const float* __restrict__ Wk,
    const float* __restrict__ Wv, const float* __restrict__ Wo)
{
    __shared__ float sm[32][33];
    int z = blockIdx.z;
    const float* W = (z == 0) ? Wq : (z == 1) ? Wk : (z == 2) ? Wv : Wo;
    int n0 = blockIdx.x * 32, k0 = blockIdx.y * 32;
    int tx = threadIdx.x, ty = threadIdx.y;
#pragma unroll
    for (int i = 0; i < 4; i++)
        sm[ty + 8 * i][tx] = W[(size_t)(k0 + ty + 8 * i) * D_MODEL + n0 + tx];
    __syncthreads();
#pragma unroll
    for (int i = 0; i < 4; i++) {
        int c = ty + 8 * i;
        float vv = sm[tx][c];
        __nv_bfloat16 h, l;
        split1(vv, h, l);
        size_t o = (size_t)(n0 + c) * D_MODEL + k0 + tx;
        g_Wth[z][o] = h;
        g_Wtl[z][o] = l;
    }
}

// V transpose + split: g_Vh [B,H,S,DK] fp32 -> g_Vth/g_Vtl [B,H,DK,S] bf16
__global__ void vtrans_kernel()
{
    __shared__ float sm[32][33];
    int bh = blockIdx.z;
    int d0 = blockIdx.x * 32, s0 = blockIdx.y * 32;
    int tx = threadIdx.x, ty = threadIdx.y;
#pragma unroll
    for (int i = 0; i < 4; i++)
        sm[ty + 8 * i][tx] = g_Vh[((size_t)bh * S_LEN + s0 + ty + 8 * i) * DK + d0 + tx];
    __syncthreads();
#pragma unroll
    for (int i = 0; i < 4; i++) {
        int dl = ty + 8 * i;
        float vv = sm[tx][dl];
        __nv_bfloat16 h, l;
        split1(vv, h, l);
        size_t o = ((size_t)bh * DK + d0 + dl) * S_LEN + s0 + tx;
        g_Vth[o] = h;
        g_Vtl[o] = l;
    }
}

// ======================= fused-pass mma.sync bf16 split GEMM =======================
// Per 32-wide K chunk: load Ah/Al/Wh/Wl tiles once, run Ah*Wh + Ah*Wl + Al*Wh.
#define BM 128
#define BN 128
#define KSTRIDE 40
#define G_TILE_B (128 * KSTRIDE * 2)     // 10240 bytes per tile
#define G_STAGE_B (4 * G_TILE_B)         // 40960 bytes per stage
#define GEMM_SMEM (2 * G_STAGE_B)        // 81920 bytes

__global__ __launch_bounds__(256, 2)
void gemm_bf16_kernel(int mode, const float* __restrict__ kpe,
                      const float* __restrict__ bq, const float* __restrict__ bk,
                      const float* __restrict__ bv, const float* __restrict__ bo,
                      float* __restrict__ out_final)
{
    extern __shared__ char sgem[];
    const uint32_t sbase = smem_u32(sgem);

    const int z = blockIdx.z;
    const __nv_bfloat16 *Ahp, *Alp, *Whp, *Wlp;
    const float* bias;
    if (mode == 0) {
        Ahp = g_Ah[z]; Alp = g_Al[z]; Whp = g_Wth[z]; Wlp = g_Wtl[z];
        bias = (z == 0) ? bq : (z == 1) ? bk : bv;
    } else {
        Ahp = g_Oh; Alp = g_Ol; Whp = g_Wth[3]; Wlp = g_Wtl[3];
        bias = bo;
    }

    const int m0 = blockIdx.y * BM;
    const int n0 = blockIdx.x * BN;
    const int tid = threadIdx.x;
    const int wid = tid >> 5, lane = tid & 31;
    const int wm = wid & 1, wn = wid >> 1;

    const int lrow = tid >> 1, lcp = tid & 1;

    auto load_chunk = [&](int kc, int buf) {
        const size_t ga = (size_t)(m0 + lrow) * D_MODEL + kc * 32 + lcp * 16;
        const size_t gb = (size_t)(n0 + lrow) * D_MODEL + kc * 32 + lcp * 16;
        const uint32_t so = sbase + buf * G_STAGE_B + (lrow * KSTRIDE + lcp * 16) * 2;
        cp16(so,                     Ahp + ga); cp16(so + 16,                Ahp + ga + 8);
        cp16(so + G_TILE_B,          Alp + ga); cp16(so + G_TILE_B + 16,     Alp + ga + 8);
        cp16(so + 2 * G_TILE_B,      Whp + gb); cp16(so + 2 * G_TILE_B + 16, Whp + gb + 8);
        cp16(so + 3 * G_TILE_B,      Wlp + gb); cp16(so + 3 * G_TILE_B + 16, Wlp + gb + 8);
        asm volatile("cp.async.commit_group;" ::: "memory");
    };

    float acc[4][4][4];
#pragma unroll
    for (int i = 0; i < 4; i++)
#pragma unroll
        for (int j = 0; j < 4; j++)
#pragma unroll
            for (int c = 0; c < 4; c++) acc[i][j][c] = 0.f;

    load_chunk(0, 0);
    load_chunk(1, 1);

    const int a_row = (lane & 15), a_koff = (lane >> 4) * 8;
    const int b_row = (lane & 7),  b_koff = ((lane >> 3) & 1) * 8;

    for (int c = 0; c < 32; c++) {
        const int buf = c & 1;
        if (c < 31) asm volatile("cp.async.wait_group 1;" ::: "memory");
        else        asm volatile("cp.async.wait_group 0;" ::: "memory");
        __syncthreads();

        const uint32_t st = sbase + buf * G_STAGE_B;
#pragma unroll
        for (int k16 = 0; k16 < 2; k16++) {
            uint32_t a[4][4], bhf[4][2], blf[4][2];
#pragma unroll
            for (int mi = 0; mi < 4; mi++)
                ldsm_x4(a[mi][0], a[mi][1], a[mi][2], a[mi][3],
                        st + ((wm * 64 + mi * 16 + a_row) * KSTRIDE + k16 * 16 + a_koff) * 2);
#pragma unroll
            for (int ni = 0; ni < 4; ni++) {
                ldsm_x2(bhf[ni][0], bhf[ni][1],
                        st + 2 * G_TILE_B + ((wn * 32 + ni * 8 + b_row) * KSTRIDE + k16 * 16 + b_koff) * 2);
                ldsm_x2(blf[ni][0], blf[ni][1],
                        st + 3 * G_TILE_B + ((wn * 32 + ni * 8 + b_row) * KSTRIDE + k16 * 16 + b_koff) * 2);
            }
#pragma unroll
            for (int ni = 0; ni < 4; ni++)
#pragma unroll
                for (int mi = 0; mi < 4; mi++)
                    mma_bf16(acc[mi][ni], a[mi], bhf[ni][0], bhf[ni][1]);
#pragma unroll
            for (int ni = 0; ni < 4; ni++)
#pragma unroll
                for (int mi = 0; mi < 4; mi++)
                    mma_bf16(acc[mi][ni], a[mi], blf[ni][0], blf[ni][1]);
            // Al tile reuses the a registers
#pragma unroll
            for (int mi = 0; mi < 4; mi++)
                ldsm_x4(a[mi][0], a[mi][1], a[mi][2], a[mi][3],
                        st + G_TILE_B + ((wm * 64 + mi * 16 + a_row) * KSTRIDE + k16 * 16 + a_koff) * 2);
#pragma unroll
            for (int ni = 0; ni < 4; ni++)
#pragma unroll
                for (int mi = 0; mi < 4; mi++)
                    mma_bf16(acc[mi][ni], a[mi], bhf[ni][0], bhf[ni][1]);
        }
        __syncthreads();
        if (c + 2 < 32) load_chunk(c + 2, buf);
    }

    const int gid = lane >> 2, tig = lane & 3;
#pragma unroll
    for (int mi = 0; mi < 4; mi++) {
#pragma unroll
        for (int half = 0; half < 2; half++) {
            const int m = m0 + wm * 64 + mi * 16 + gid + half * 8;
            const int bb = m >> 11, s = m & 2047;
#pragma unroll
            for (int ni = 0; ni < 4; ni++) {
                const int n = n0 + wn * 32 + ni * 8 + tig * 2;
                float c0 = acc[mi][ni][half * 2 + 0] + bias[n];
                float c1 = acc[mi][ni][half * 2 + 1] + bias[n + 1];
                if (mode == 0) {
                    const int h = n >> 6, d = n & 63;
                    size_t o = (((size_t)bb * N_HEADS + h) * S_LEN + s) * DK + d;
                    if (z == 0) {
                        __nv_bfloat16 h0,l0,h1,l1;
                        split1(c0 * 0.125f, h0, l0);
                        split1(c1 * 0.125f, h1, l1);
                        *(__nv_bfloat162*)&g_Qbh[o] = __nv_bfloat162(h0, h1);
                        *(__nv_bfloat162*)&g_Qbl[o] = __nv_bfloat162(l0, l1);
                    } else if (z == 1) {
                        c0 += kpe[((size_t)h * DK + d) * S_LEN + s];
                        c1 += kpe[((size_t)h * DK + d + 1) * S_LEN + s];
                        __nv_bfloat16 h0,l0,h1,l1;
                        split1(c0, h0, l0);
                        split1(c1, h1, l1);
                        *(__nv_bfloat162*)&g_Kbh[o] = __nv_bfloat162(h0, h1);
                        *(__nv_bfloat162*)&g_Kbl[o] = __nv_bfloat162(l0, l1);
                    } else {
                        *(float2*)&g_Vh[o] = make_float2(c0, c1);
                    }
                } else {
                    *(float2*)&out_final[(size_t)m * D_MODEL + n] = make_float2(c0, c1);
                }
            }
        }
    }
}

// ======================= register-resident flash attention, 2-way split-K =======================
#define AT_KSTR 72
#define AQ_OFF  0
#define AKH_OFF 18432
#define AKL_OFF (AKH_OFF + 2 * 9216)
#define AVH_OFF (AKL_OFF + 2 * 9216)
#define AVL_OFF (AVH_OFF + 2 * 9216)
#define ATTN_SMEM3 (AVL_OFF + 2 * 9216)   // 92160 B
#define SPLIT_TILES 16                    // 16 tiles of 64 keys per split

__global__ __launch_bounds__(256)
void attn_mma_kernel()
{
    extern __shared__ char smc[];
    const uint32_t base = smem_u32(smc);

    const int tid = threadIdx.x;
    const int wid = tid >> 5, lane = tid & 31;
    const int q0 = blockIdx.x * 128;
    const int h = blockIdx.y;
    const int bz = blockIdx.z >> 1, sp = blockIdx.z & 1;
    const int bh = bz * N_HEADS + h;
    const int T0 = sp * SPLIT_TILES;

    const int a_row = (lane & 15), a_koff = (lane >> 4) * 8;
    const int b_row4 = (lane & 7) + ((lane >> 4) << 3);
    const int b_koff4 = ((lane >> 3) & 1) * 8;
    const int gid = lane >> 2, tig = lane & 3;

    // ---- load Q fragments ----
    uint32_t qh[4][4], ql[4][4];
    for (int r = 0; r < 2; r++) {
        const __nv_bfloat16* Qg = r ? g_Qbl : g_Qbh;
#pragma unroll
        for (int it = 0; it < 4; it++) {
            int idx = tid + it * 256;
            int row = idx >> 3, cp = idx & 7;
            cp16(base + AQ_OFF + (row * AT_KSTR + cp * 8) * 2,
                 Qg + ((size_t)bh * S_LEN + q0 + row) * DK + cp * 8);
        }
        asm volatile("cp.async.commit_group;" ::: "memory");
        asm volatile("cp.async.wait_group 0;" ::: "memory");
        __syncthreads();
#pragma unroll
        for (int k16 = 0; k16 < 4; k16++) {
            uint32_t* f = r ? ql[k16] : qh[k16];
            ldsm_x4(f[0], f[1], f[2], f[3],
                    base + AQ_OFF + ((wid * 16 + a_row) * AT_KSTR + k16 * 16 + a_koff) * 2);
        }
        __syncthreads();
    }

    auto load_kv = [&](int T, int bufx) {
        const int t0 = T * 64;
        const __nv_bfloat16* srcs[4] = { g_Kbh, g_Kbl, g_Vth, g_Vtl };
        const uint32_t dsts[4] = { AKH_OFF, AKL_OFF, AVH_OFF, AVL_OFF };
#pragma unroll
        for (int arr = 0; arr < 4; arr++)
#pragma unroll
            for (int hf = 0; hf < 2; hf++) {
                int rem = tid + hf * 256;
                int row = rem >> 3, cp = rem & 7;
                const __nv_bfloat16* src;
                if (arr < 2) src = srcs[arr] + ((size_t)bh * S_LEN + t0 + row) * DK + cp * 8;
                else         src = srcs[arr] + ((size_t)bh * DK + row) * S_LEN + t0 + cp * 8;
                cp16(base + dsts[arr] + bufx * 9216 + (row * AT_KSTR + cp * 8) * 2, src);
            }
        asm volatile("cp.async.commit_group;" ::: "memory");
    };

    float oacc[8][4];
#pragma unroll
    for (int ni = 0; ni < 8; ni++)
#pragma unroll
        for (int c = 0; c < 4; c++) oacc[ni][c] = 0.f;
    float m0 = -1e30f, m1 = -1e30f, l0 = 0.f, l1 = 0.f;

    load_kv(T0, 0);

#pragma unroll 1
    for (int Ti = 0; Ti < SPLIT_TILES; Ti++) {
        const int buf = Ti & 1;
        asm volatile("cp.async.wait_group 0;" ::: "memory");
        __syncthreads();
        if (Ti + 1 < SPLIT_TILES) load_kv(T0 + Ti + 1, buf ^ 1);

        const uint32_t khb = base + AKH_OFF + buf * 9216;
        const uint32_t klb = base + AKL_OFF + buf * 9216;
        const uint32_t vhb = base + AVH_OFF + buf * 9216;
        const uint32_t vlb = base + AVL_OFF + buf * 9216;

        // ---- QK^T: S = Qh*Kh + Qh*Kl + Ql*Kh ----
        float sacc[8][4];
#pragma unroll
        for (int ni = 0; ni < 8; ni++)
#pragma unroll
            for (int c = 0; c < 4; c++) sacc[ni][c] = 0.f;

#pragma unroll
        for (int kd = 0; kd < 4; kd++) {
            uint32_t kf[4][4];
#pragma unroll
            for (int np = 0; np < 4; np++)
                ldsm_x4(kf[np][0], kf[np][1], kf[np][2], kf[np][3],
                        khb + ((np * 16 + b_row4) * AT_KSTR + kd * 16 + b_koff4) * 2);
#pragma unroll
            for (int np = 0; np < 4; np++) {
                mma_bf16(sacc[2 * np],     qh[kd], kf[np][0], kf[np][1]);
                mma_bf16(sacc[2 * np + 1], qh[kd], kf[np][2], kf[np][3]);
            }
#pragma unroll
            for (int np = 0; np < 4; np++) {
                mma_bf16(sacc[2 * np],     ql[kd], kf[np][0], kf[np][1]);
                mma_bf16(sacc[2 * np + 1], ql[kd], kf[np][2], kf[np][3]);
            }
#pragma unroll
            for (int np = 0; np < 4; np++)
                ldsm_x4(kf[np][0], kf[np][1], kf[np][2], kf[np][3],
                        klb + ((np * 16 + b_row4) * AT_KSTR + kd * 16 + b_koff4) * 2);
#pragma unroll
            for (int np = 0; np < 4; np++) {
                mma_bf16(sacc[2 * np],     qh[kd], kf[np][0], kf[np][1]);
                mma_bf16(sacc[2 * np + 1], qh[kd], kf[np][2], kf[np][3]);
            }
        }

        // ---- register softmax ----
        float mx0 = -1e30f, mx1 = -1e30f;
#pragma unroll
        for (int ni = 0; ni < 8; ni++) {
            mx0 = fmaxf(mx0, fmaxf(sacc[ni][0], sacc[ni][1]));
            mx1 = fmaxf(mx1, fmaxf(sacc[ni][2], sacc[ni][3]));
        }
        mx0 = fmaxf(mx0, __shfl_xor_sync(0xffffffffu, mx0, 1));
        mx0 = fmaxf(mx0, __shfl_xor_sync(0xffffffffu, mx0, 2));
        mx1 = fmaxf(mx1, __shfl_xor_sync(0xffffffffu, mx1, 1));
        mx1 = fmaxf(mx1, __shfl_xor_sync(0xffffffffu, mx1, 2));

        const float mn0 = fmaxf(m0, mx0), mn1 = fmaxf(m1, mx1);
        const float cr0 = __expf(m0 - mn0), cr1 = __expf(m1 - mn1);
        m0 = mn0; m1 = mn1;

        float s0 = 0.f, s1 = 0.f;
#pragma unroll
        for (int ni = 0; ni < 8; ni++) {
            sacc[ni][0] = __expf(sacc[ni][0] - mn0);
            sacc[ni][1] = __expf(sacc[ni][1] - mn0);
            sacc[ni][2] = __expf(sacc[ni][2] - mn1);
            sacc[ni][3] = __expf(sacc[ni][3] - mn1);
            s0 += sacc[ni][0] + sacc[ni][1];
            s1 += sacc[ni][2] + sacc[ni][3];
        }
        s0 += __shfl_xor_sync(0xffffffffu, s0, 1);
        s0 += __shfl_xor_sync(0xffffffffu, s0, 2);
        s1 += __shfl_xor_sync(0xffffffffu, s1, 1);
        s1 += __shfl_xor_sync(0xffffffffu, s1, 2);
        l0 = l0 * cr0 + s0;
        l1 = l1 * cr1 + s1;

#pragma unroll
        for (int ni = 0; ni < 8; ni++) {
            oacc[ni][0] *= cr0; oacc[ni][1] *= cr0;
            oacc[ni][2] *= cr1; oacc[ni][3] *= cr1;
        }

        // ---- P fragments ----
        uint32_t ph[4][4], pl[4][4];
#pragma unroll
        for (int kt = 0; kt < 4; kt++) {
            const float* e0 = sacc[2 * kt];
            const float* e1 = sacc[2 * kt + 1];
            __nv_bfloat16 h00, l00, h01, l01, h02, l02, h03, l03;
            __nv_bfloat16 h10, l10, h11, l11, h12, l12, h13, l13;
            split1(e0[0], h00, l00); split1(e0[1], h01, l01);
            split1(e0[2], h02, l02); split1(e0[3], h03, l03);
            split1(e1[0], h10, l10); split1(e1[1], h11, l11);
            split1(e1[2], h12, l12); split1(e1[3], h13, l13);
            ph[kt][0] = pack_bf(h00, h01); ph[kt][1] = pack_bf(h02, h03);
            ph[kt][2] = pack_bf(h10, h11); ph[kt][3] = pack_bf(h12, h13);
            pl[kt][0] = pack_bf(l00, l01); pl[kt][1] = pack_bf(l02, l03);
            pl[kt][2] = pack_bf(l10, l11); pl[kt][3] = pack_bf(l12, l13);
        }

        // ---- PV: O += Ph*Vh + Pl*Vh + Ph*Vl ----
#pragma unroll
        for (int kt = 0; kt < 4; kt++) {
            uint32_t vf[4][4];
#pragma unroll
            for (int np = 0; np < 4; np++)
                ldsm_x4(vf[np][0], vf[np][1], vf[np][2], vf[np][3],
                        vhb + ((np * 16 + b_row4) * AT_KSTR + kt * 16 + b_koff4) * 2);
#pragma unroll
            for (int np = 0; np < 4; np++) {
                mma_bf16(oacc[2 * np],     ph[kt], vf[np][0], vf[np][1]);
                mma_bf16(oacc[2 * np + 1], ph[kt], vf[np][2], vf[np][3]);
            }
#pragma unroll
            for (int np = 0; np < 4; np++) {
                mma_bf16(oacc[2 * np],     pl[kt], vf[np][0], vf[np][1]);
                mma_bf16(oacc[2 * np + 1], pl[kt], vf[np][2], vf[np][3]);
            }
#pragma unroll
            for (int np = 0; np < 4; np++)
                ldsm_x4(vf[np][0], vf[np][1], vf[np][2], vf[np][3],
                        vlb + ((np * 16 + b_row4) * AT_KSTR + kt * 16 + b_koff4) * 2);
#pragma unroll
            for (int np = 0; np < 4; np++) {
                mma_bf16(oacc[2 * np],     ph[kt], vf[np][0], vf[np][1]);
                mma_bf16(oacc[2 * np + 1], ph[kt], vf[np][2], vf[np][3]);
            }
        }
    }

    // ---- epilogue: raw partials + (m, l) ----
#pragma unroll
    for (int hf = 0; hf < 2; hf++) {
        const int s = q0 + wid * 16 + gid + hf * 8;
        const size_t row = (size_t)bh * S_LEN + s;
#pragma unroll
        for (int ni = 0; ni < 8; ni++) {
            const int d = ni * 8 + tig * 2;
            *(float2*)&g_Opart[sp][row * DK + d] =
                make_float2(oacc[ni][hf * 2 + 0], oacc[ni][hf * 2 + 1]);
        }
        if (tig == 0)
            g_MLpart[sp][row] = make_float2(hf ? m1 : m0, hf ? l1 : l0);
    }
}

// combine the two split-K halves -> bf16 hi/lo attention output
__global__ __launch_bounds__(256) void attn_combine_kernel()
{
    size_t idx = ((size_t)blockIdx.x * 256 + threadIdx.x) * 4;
    size_t r = idx >> 6;
    int d = (int)(idx & 63);
    float2 ml0 = g_MLpart[0][r], ml1 = g_MLpart[1][r];
    float m = fmaxf(ml0.x, ml1.x);
    float c0 = __expf(ml0.x - m), c1 = __expf(ml1.x - m);
    float inv = 1.f / (c0 * ml0.y + c1 * ml1.y);
    float4 o0 = *(float4*)&g_Opart[0][idx];
    float4 o1 = *(float4*)&g_Opart[1][idx];
    float v0 = (c0 * o0.x + c1 * o1.x) * inv;
    float v1 = (c0 * o0.y + c1 * o1.y) * inv;
    float v2 = (c0 * o0.z + c1 * o1.z) * inv;
    float v3 = (c0 * o0.w + c1 * o1.w) * inv;

    int bz = (int)(r / (N_HEADS * S_LEN));
    int h  = (int)((r / S_LEN) % N_HEADS);
    int s  = (int)(r % S_LEN);
    size_t o = ((size_t)bz * S_LEN + s) * D_MODEL + h * DK + d;

    __nv_bfloat16 h0,l0,h1,l1,h2,l2,h3,l3;
    split1(v0,h0,l0); split1(v1,h1,l1); split1(v2,h2,l2); split1(v3,h3,l3);
    *(__nv_bfloat162*)&g_Oh[o]     = __nv_bfloat162(h0, h1);
    *(__nv_bfloat162*)&g_Oh[o + 2] = __nv_bfloat162(h2, h3);
    *(__nv_bfloat162*)&g_Ol[o]     = __nv_bfloat162(l0, l1);
    *(__nv_bfloat162*)&g_Ol[o + 2] = __nv_bfloat162(l2, l3);
}

// =====================================================================
extern "C" void kernel_launch(void* const* d_in, const int* in_sizes, int n_in,
                              void* d_out, int out_size)
{
    const float* q   = (const float*)d_in[0];
    const float* k   = (const float*)d_in[1];
    const float* v   = (const float*)d_in[2];
    const float* kpe = (const float*)d_in[3];
    const float* Wq  = (const float*)d_in[4];
    const float* bq  = (const float*)d_in[5];
    const float* Wk  = (const float*)d_in[6];
    const float* bk  = (const float*)d_in[7];
    const float* Wv  = (const float*)d_in[8];
    const float* bv  = (const float*)d_in[9];
    const float* Wo  = (const float*)d_in[10];
    const float* bo  = (const float*)d_in[11];
    float* out = (float*)d_out;

    cudaFuncSetAttribute(attn_mma_kernel, cudaFuncAttributeMaxDynamicSharedMemorySize,
                         ATTN_SMEM3);
    cudaFuncSetAttribute(gemm_bf16_kernel, cudaFuncAttributeMaxDynamicSharedMemorySize,
                         GEMM_SMEM);

    // prep: split inputs + weights to bf16 hi/lo
    dim3 gs(M_ROWS * D_MODEL / 1024, 3);
    split_qkv_kernel<<<gs, 256>>>(q, k, v);
    dim3 gw(32, 32, 4);
    splitW_kernel<<<gw, dim3(32, 8)>>>(Wq, Wk, Wv, Wo);

    // Q/K/V projections
    dim3 gp(D_MODEL / BN, M_ROWS / BM, 3);
    gemm_bf16_kernel<<<gp, 256, GEMM_SMEM>>>(0, kpe, bq, bk, bv, bo, out);

    // V transpose + split
    dim3 gv(DK / 32, S_LEN / 32, B_SIZE * N_HEADS);
    vtrans_kernel<<<gv, dim3(32, 8)>>>();

    // attention (tensor cores, register-resident P, 2-way split-K)
    dim3 ga(S_LEN / 128, N_HEADS, B_SIZE * 2);
    attn_mma_kernel<<<ga, 256, ATTN_SMEM3>>>();
    attn_combine_kernel<<<BHS * DK / 1024, 256>>>();

    // output projection
    dim3 go(D_MODEL / BN, M_ROWS / BM, 1);
    gemm_bf16_kernel<<<go, 256, GEMM_SMEM>>>(1, kpe, bq, bk, bv, bo, out);
}

// round 8
// speedup vs baseline: 1.2821x; 1.2821x over previous
#include <cuda_runtime.h>
#include <cuda_bf16.h>
#include <cstdint>

#define D_MODEL 1024
#define N_HEADS 16
#define DK      64
#define B_SIZE  2
#define S_LEN   2048
#define M_ROWS  (B_SIZE * S_LEN)   // 4096
#define BHS     (B_SIZE * N_HEADS * S_LEN)

// ---------------- scratch ----------------
__device__ float g_Vh[B_SIZE * N_HEADS * S_LEN * DK];          // V head-split fp32 (pre-transpose)

__device__ __nv_bfloat16 g_Ah[3][(size_t)M_ROWS * D_MODEL];
__device__ __nv_bfloat16 g_Al[3][(size_t)M_ROWS * D_MODEL];
__device__ __nv_bfloat16 g_Oh[(size_t)M_ROWS * D_MODEL];       // attn out hi
__device__ __nv_bfloat16 g_Ol[(size_t)M_ROWS * D_MODEL];       // attn out lo
__device__ __nv_bfloat16 g_Wth[4][(size_t)D_MODEL * D_MODEL];  // W^T hi [n][k]
__device__ __nv_bfloat16 g_Wtl[4][(size_t)D_MODEL * D_MODEL];  // W^T lo [n][k]

// attention operands (bf16 split)
__device__ __nv_bfloat16 g_Qbh[(size_t)M_ROWS * D_MODEL];      // [B,H,S,DK] hi, scaled 1/8
__device__ __nv_bfloat16 g_Qbl[(size_t)M_ROWS * D_MODEL];
__device__ __nv_bfloat16 g_Kbh[(size_t)M_ROWS * D_MODEL];      // [B,H,S,DK] hi (K + kpe)
__device__ __nv_bfloat16 g_Kbl[(size_t)M_ROWS * D_MODEL];
__device__ __nv_bfloat16 g_Vth[(size_t)M_ROWS * D_MODEL];      // [B,H,DK,S] hi (transposed)
__device__ __nv_bfloat16 g_Vtl[(size_t)M_ROWS * D_MODEL];

// split-K attention partials
__device__ float  g_Opart[2][(size_t)BHS * DK];                // raw (unnormalized) O
__device__ float2 g_MLpart[2][BHS];                            // (m, l) per row

// ======================= helpers =======================
__device__ __forceinline__ uint32_t smem_u32(const void* p) {
    uint32_t a;
    asm("{ .reg .u64 t; cvta.to.shared.u64 t, %1; cvt.u32.u64 %0, t; }" : "=r"(a) : "l"(p));
    return a;
}
__device__ __forceinline__ void cp16(uint32_t dst, const void* src) {
    asm volatile("cp.async.cg.shared.global [%0], [%1], 16;" :: "r"(dst), "l"(src));
}
__device__ __forceinline__ void ldsm_x4(uint32_t& r0, uint32_t& r1, uint32_t& r2, uint32_t& r3, uint32_t addr) {
    asm volatile("ldmatrix.sync.aligned.m8n8.x4.shared.b16 {%0,%1,%2,%3}, [%4];"
        : "=r"(r0), "=r"(r1), "=r"(r2), "=r"(r3) : "r"(addr));
}
__device__ __forceinline__ void ldsm_x2(uint32_t& r0, uint32_t& r1, uint32_t addr) {
    asm volatile("ldmatrix.sync.aligned.m8n8.x2.shared.b16 {%0,%1}, [%2];"
        : "=r"(r0), "=r"(r1) : "r"(addr));
}
__device__ __forceinline__ void mma_bf16(float* c, const uint32_t* a, uint32_t b0, uint32_t b1) {
    asm volatile("mma.sync.aligned.m16n8k16.row.col.f32.bf16.bf16.f32 "
        "{%0,%1,%2,%3}, {%4,%5,%6,%7}, {%8,%9}, {%0,%1,%2,%3};"
        : "+f"(c[0]), "+f"(c[1]), "+f"(c[2]), "+f"(c[3])
        : "r"(a[0]), "r"(a[1]), "r"(a[2]), "r"(a[3]), "r"(b0), "r"(b1));
}
__device__ __forceinline__ void split1(float x, __nv_bfloat16& h, __nv_bfloat16& l) {
    h = __float2bfloat16_rn(x);
    l = __float2bfloat16_rn(x - __bfloat162float(h));
}
__device__ __forceinline__ uint32_t pack_bf(__nv_bfloat16 a, __nv_bfloat16 b) {
    __nv_bfloat162 t(a, b);
    return *(uint32_t*)&t;
}

// ======================= split prep kernels =======================
__global__ __launch_bounds__(256) void split_qkv_kernel(
    const float* __restrict__ q, const float* __restrict__ k, const float* __restrict__ v)
{
    int z = blockIdx.y;
    const float* src = (z == 0) ? q : (z == 1) ? k : v;
    __nv_bfloat16* hi = g_Ah[z];
    __nv_bfloat16* lo = g_Al[z];
    size_t i = ((size_t)blockIdx.x * 256 + threadIdx.x) * 4;
    float4 a = *(const float4*)(src + i);
    __nv_bfloat16 h0,h1,h2,h3,l0,l1,l2,l3;
    split1(a.x,h0,l0); split1(a.y,h1,l1); split1(a.z,h2,l2); split1(a.w,h3,l3);
    *(__nv_bfloat162*)(hi+i)   = __nv_bfloat162(h0,h1);
    *(__nv_bfloat162*)(hi+i+2) = __nv_bfloat162(h2,h3);
    *(__nv_bfloat162*)(lo+i)   = __nv_bfloat162(l0,l1);
    *(__nv_bfloat162*)(lo+i+2) = __nv_bfloat162(l2,l3);
}

__global__ void splitW_kernel(
    const float* __restrict__ Wq, const float* __restrict__ Wk,
    const float* __restrict__ Wv, const float* __restrict__ Wo)
{
    __shared__ float sm[32][33];
    int z = blockIdx.z;
    const float* W = (z == 0) ? Wq : (z == 1) ? Wk : (z == 2) ? Wv : Wo;
    int n0 = blockIdx.x * 32, k0 = blockIdx.y * 32;
    int tx = threadIdx.x, ty = threadIdx.y;
#pragma unroll
    for (int i = 0; i < 4; i++)
        sm[ty + 8 * i][tx] = W[(size_t)(k0 + ty + 8 * i) * D_MODEL + n0 + tx];
    __syncthreads();
#pragma unroll
    for (int i = 0; i < 4; i++) {
        int c = ty + 8 * i;
        float vv = sm[tx][c];
        __nv_bfloat16 h, l;
        split1(vv, h, l);
        size_t o = (size_t)(n0 + c) * D_MODEL + k0 + tx;
        g_Wth[z][o] = h;
        g_Wtl[z][o] = l;
    }
}

// V transpose + split: g_Vh [B,H,S,DK] fp32 -> g_Vth/g_Vtl [B,H,DK,S] bf16
__global__ void vtrans_kernel()
{
    __shared__ float sm[32][33];
    int bh = blockIdx.z;
    int d0 = blockIdx.x * 32, s0 = blockIdx.y * 32;
    int tx = threadIdx.x, ty = threadIdx.y;
#pragma unroll
    for (int i = 0; i < 4; i++)
        sm[ty + 8 * i][tx] = g_Vh[((size_t)bh * S_LEN + s0 + ty + 8 * i) * DK + d0 + tx];
    __syncthreads();
#pragma unroll
    for (int i = 0; i < 4; i++) {
        int dl = ty + 8 * i;
        float vv = sm[tx][dl];
        __nv_bfloat16 h, l;
        split1(vv, h, l);
        size_t o = ((size_t)bh * DK + d0 + dl) * S_LEN + s0 + tx;
        g_Vth[o] = h;
        g_Vtl[o] = l;
    }
}

// ======================= mma.sync bf16 split GEMM (R6 proven version) =======================
#define BM 128
#define BN 128
#define BK 32
#define KSTRIDE 40

__global__ __launch_bounds__(256)
void gemm_bf16_kernel(int mode, const float* __restrict__ kpe,
                      const float* __restrict__ bq, const float* __restrict__ bk,
                      const float* __restrict__ bv, const float* __restrict__ bo,
                      float* __restrict__ out_final)
{
    __shared__ __nv_bfloat16 sA[2][BM * KSTRIDE];
    __shared__ __nv_bfloat16 sB[2][BN * KSTRIDE];

    const int z = blockIdx.z;
    const __nv_bfloat16 *Ahp, *Alp, *Whp, *Wlp;
    const float* bias;
    if (mode == 0) {
        Ahp = g_Ah[z]; Alp = g_Al[z]; Whp = g_Wth[z]; Wlp = g_Wtl[z];
        bias = (z == 0) ? bq : (z == 1) ? bk : bv;
    } else {
        Ahp = g_Oh; Alp = g_Ol; Whp = g_Wth[3]; Wlp = g_Wtl[3];
        bias = bo;
    }

    const int m0 = blockIdx.y * BM;
    const int n0 = blockIdx.x * BN;
    const int tid = threadIdx.x;
    const int wid = tid >> 5, lane = tid & 31;
    const int wm = wid & 1, wn = wid >> 1;

    const uint32_t sA0 = smem_u32(sA[0]);
    const uint32_t sB0 = smem_u32(sB[0]);
    const int lrow = tid >> 1, lcp = tid & 1;

    auto load_step = [&](int step, int buf) {
        int p = step >> 5, kc = (step & 31) * BK;
        const __nv_bfloat16* As = (p < 2) ? Ahp : Alp;
        const __nv_bfloat16* Bs = (p == 1) ? Wlp : Whp;
        const __nv_bfloat16* ag = As + (size_t)(m0 + lrow) * D_MODEL + kc + lcp * 16;
        const __nv_bfloat16* bg = Bs + (size_t)(n0 + lrow) * D_MODEL + kc + lcp * 16;
        uint32_t sa = sA0 + buf * (BM * KSTRIDE * 2) + (lrow * KSTRIDE + lcp * 16) * 2;
        uint32_t sb = sB0 + buf * (BN * KSTRIDE * 2) + (lrow * KSTRIDE + lcp * 16) * 2;
        cp16(sa, ag);       cp16(sa + 16, ag + 8);
        cp16(sb, bg);       cp16(sb + 16, bg + 8);
        asm volatile("cp.async.commit_group;" ::: "memory");
    };

    float acc[4][4][4];
#pragma unroll
    for (int i = 0; i < 4; i++)
#pragma unroll
        for (int j = 0; j < 4; j++)
#pragma unroll
            for (int c = 0; c < 4; c++) acc[i][j][c] = 0.f;

    load_step(0, 0);
    load_step(1, 1);

    const int a_row = (lane & 15), a_koff = (lane >> 4) * 8;
    const int b_row = (lane & 7),  b_koff = ((lane >> 3) & 1) * 8;

    for (int step = 0; step < 96; step++) {
        const int buf = step & 1;
        if (step < 95) asm volatile("cp.async.wait_group 1;" ::: "memory");
        else           asm volatile("cp.async.wait_group 0;" ::: "memory");
        __syncthreads();

        const uint32_t abase = sA0 + buf * (BM * KSTRIDE * 2);
        const uint32_t bbase = sB0 + buf * (BN * KSTRIDE * 2);
#pragma unroll
        for (int k16 = 0; k16 < BK; k16 += 16) {
            uint32_t a[4][4];
#pragma unroll
            for (int mi = 0; mi < 4; mi++)
                ldsm_x4(a[mi][0], a[mi][1], a[mi][2], a[mi][3],
                        abase + ((wm * 64 + mi * 16 + a_row) * KSTRIDE + k16 + a_koff) * 2);
#pragma unroll
            for (int ni = 0; ni < 4; ni++) {
                uint32_t b0, b1;
                ldsm_x2(b0, b1,
                        bbase + ((wn * 32 + ni * 8 + b_row) * KSTRIDE + k16 + b_koff) * 2);
#pragma unroll
                for (int mi = 0; mi < 4; mi++)
                    mma_bf16(acc[mi][ni], a[mi], b0, b1);
            }
        }
        __syncthreads();
        if (step + 2 < 96) load_step(step + 2, buf);
    }

    const int gid = lane >> 2, tig = lane & 3;
#pragma unroll
    for (int mi = 0; mi < 4; mi++) {
#pragma unroll
        for (int half = 0; half < 2; half++) {
            const int m = m0 + wm * 64 + mi * 16 + gid + half * 8;
            const int bb = m >> 11, s = m & 2047;
#pragma unroll
            for (int ni = 0; ni < 4; ni++) {
                const int n = n0 + wn * 32 + ni * 8 + tig * 2;
                float c0 = acc[mi][ni][half * 2 + 0] + bias[n];
                float c1 = acc[mi][ni][half * 2 + 1] + bias[n + 1];
                if (mode == 0) {
                    const int h = n >> 6, d = n & 63;
                    size_t o = (((size_t)bb * N_HEADS + h) * S_LEN + s) * DK + d;
                    if (z == 0) {
                        __nv_bfloat16 h0,l0,h1,l1;
                        split1(c0 * 0.125f, h0, l0);
                        split1(c1 * 0.125f, h1, l1);
                        *(__nv_bfloat162*)&g_Qbh[o] = __nv_bfloat162(h0, h1);
                        *(__nv_bfloat162*)&g_Qbl[o] = __nv_bfloat162(l0, l1);
                    } else if (z == 1) {
                        c0 += kpe[((size_t)h * DK + d) * S_LEN + s];
                        c1 += kpe[((size_t)h * DK + d + 1) * S_LEN + s];
                        __nv_bfloat16 h0,l0,h1,l1;
                        split1(c0, h0, l0);
                        split1(c1, h1, l1);
                        *(__nv_bfloat162*)&g_Kbh[o] = __nv_bfloat162(h0, h1);
                        *(__nv_bfloat162*)&g_Kbl[o] = __nv_bfloat162(l0, l1);
                    } else {
                        *(float2*)&g_Vh[o] = make_float2(c0, c1);
                    }
                } else {
                    *(float2*)&out_final[(size_t)m * D_MODEL + n] = make_float2(c0, c1);
                }
            }
        }
    }
}

// ======================= register-resident flash attention, 2-way split-K =======================
#define AT_KSTR 72
#define AQ_OFF  0
#define AKH_OFF 18432
#define AKL_OFF (AKH_OFF + 2 * 9216)
#define AVH_OFF (AKL_OFF + 2 * 9216)
#define AVL_OFF (AVH_OFF + 2 * 9216)
#define ATTN_SMEM3 (AVL_OFF + 2 * 9216)   // 92160 B
#define SPLIT_TILES 16                    // 16 tiles of 64 keys per split

__global__ __launch_bounds__(256)
void attn_mma_kernel()
{
    extern __shared__ char smc[];
    const uint32_t base = smem_u32(smc);

    const int tid = threadIdx.x;
    const int wid = tid >> 5, lane = tid & 31;
    const int q0 = blockIdx.x * 128;
    const int h = blockIdx.y;
    const int bz = blockIdx.z >> 1, sp = blockIdx.z & 1;
    const int bh = bz * N_HEADS + h;
    const int T0 = sp * SPLIT_TILES;

    const int a_row = (lane & 15), a_koff = (lane >> 4) * 8;
    const int b_row4 = (lane & 7) + ((lane >> 4) << 3);
    const int b_koff4 = ((lane >> 3) & 1) * 8;
    const int gid = lane >> 2, tig = lane & 3;

    // ---- load Q fragments ----
    uint32_t qh[4][4], ql[4][4];
    for (int r = 0; r < 2; r++) {
        const __nv_bfloat16* Qg = r ? g_Qbl : g_Qbh;
#pragma unroll
        for (int it = 0; it < 4; it++) {
            int idx = tid + it * 256;
            int row = idx >> 3, cp = idx & 7;
            cp16(base + AQ_OFF + (row * AT_KSTR + cp * 8) * 2,
                 Qg + ((size_t)bh * S_LEN + q0 + row) * DK + cp * 8);
        }
        asm volatile("cp.async.commit_group;" ::: "memory");
        asm volatile("cp.async.wait_group 0;" ::: "memory");
        __syncthreads();
#pragma unroll
        for (int k16 = 0; k16 < 4; k16++) {
            uint32_t* f = r ? ql[k16] : qh[k16];
            ldsm_x4(f[0], f[1], f[2], f[3],
                    base + AQ_OFF + ((wid * 16 + a_row) * AT_KSTR + k16 * 16 + a_koff) * 2);
        }
        __syncthreads();
    }

    auto load_kv = [&](int T, int bufx) {
        const int t0 = T * 64;
        const __nv_bfloat16* srcs[4] = { g_Kbh, g_Kbl, g_Vth, g_Vtl };
        const uint32_t dsts[4] = { AKH_OFF, AKL_OFF, AVH_OFF, AVL_OFF };
#pragma unroll
        for (int arr = 0; arr < 4; arr++)
#pragma unroll
            for (int hf = 0; hf < 2; hf++) {
                int rem = tid + hf * 256;
                int row = rem >> 3, cp = rem & 7;
                const __nv_bfloat16* src;
                if (arr < 2) src = srcs[arr] + ((size_t)bh * S_LEN + t0 + row) * DK + cp * 8;
                else         src = srcs[arr] + ((size_t)bh * DK + row) * S_LEN + t0 + cp * 8;
                cp16(base + dsts[arr] + bufx * 9216 + (row * AT_KSTR + cp * 8) * 2, src);
            }
        asm volatile("cp.async.commit_group;" ::: "memory");
    };

    float oacc[8][4];
#pragma unroll
    for (int ni = 0; ni < 8; ni++)
#pragma unroll
        for (int c = 0; c < 4; c++) oacc[ni][c] = 0.f;
    float m0 = -1e30f, m1 = -1e30f, l0 = 0.f, l1 = 0.f;

    load_kv(T0, 0);

#pragma unroll 1
    for (int Ti = 0; Ti < SPLIT_TILES; Ti++) {
        const int buf = Ti & 1;
        asm volatile("cp.async.wait_group 0;" ::: "memory");
        __syncthreads();
        if (Ti + 1 < SPLIT_TILES) load_kv(T0 + Ti + 1, buf ^ 1);

        const uint32_t khb = base + AKH_OFF + buf * 9216;
        const uint32_t klb = base + AKL_OFF + buf * 9216;
        const uint32_t vhb = base + AVH_OFF + buf * 9216;
        const uint32_t vlb = base + AVL_OFF + buf * 9216;

        // ---- QK^T: S = Qh*Kh + Qh*Kl + Ql*Kh ----
        float sacc[8][4];
#pragma unroll
        for (int ni = 0; ni < 8; ni++)
#pragma unroll
            for (int c = 0; c < 4; c++) sacc[ni][c] = 0.f;

#pragma unroll
        for (int kd = 0; kd < 4; kd++) {
            uint32_t kf[4][4];
#pragma unroll
            for (int np = 0; np < 4; np++)
                ldsm_x4(kf[np][0], kf[np][1], kf[np][2], kf[np][3],
                        khb + ((np * 16 + b_row4) * AT_KSTR + kd * 16 + b_koff4) * 2);
#pragma unroll
            for (int np = 0; np < 4; np++) {
                mma_bf16(sacc[2 * np],     qh[kd], kf[np][0], kf[np][1]);
                mma_bf16(sacc[2 * np + 1], qh[kd], kf[np][2], kf[np][3]);
            }
#pragma unroll
            for (int np = 0; np < 4; np++) {
                mma_bf16(sacc[2 * np],     ql[kd], kf[np][0], kf[np][1]);
                mma_bf16(sacc[2 * np + 1], ql[kd], kf[np][2], kf[np][3]);
            }
#pragma unroll
            for (int np = 0; np < 4; np++)
                ldsm_x4(kf[np][0], kf[np][1], kf[np][2], kf[np][3],
                        klb + ((np * 16 + b_row4) * AT_KSTR + kd * 16 + b_koff4) * 2);
#pragma unroll
            for (int np = 0; np < 4; np++) {
                mma_bf16(sacc[2 * np],     qh[kd], kf[np][0], kf[np][1]);
                mma_bf16(sacc[2 * np + 1], qh[kd], kf[np][2], kf[np][3]);
            }
        }

        // ---- register softmax ----
        float mx0 = -1e30f, mx1 = -1e30f;
#pragma unroll
        for (int ni = 0; ni < 8; ni++) {
            mx0 = fmaxf(mx0, fmaxf(sacc[ni][0], sacc[ni][1]));
            mx1 = fmaxf(mx1, fmaxf(sacc[ni][2], sacc[ni][3]));
        }
        mx0 = fmaxf(mx0, __shfl_xor_sync(0xffffffffu, mx0, 1));
        mx0 = fmaxf(mx0, __shfl_xor_sync(0xffffffffu, mx0, 2));
        mx1 = fmaxf(mx1, __shfl_xor_sync(0xffffffffu, mx1, 1));
        mx1 = fmaxf(mx1, __shfl_xor_sync(0xffffffffu, mx1, 2));

        const float mn0 = fmaxf(m0, mx0), mn1 = fmaxf(m1, mx1);
        const float cr0 = __expf(m0 - mn0), cr1 = __expf(m1 - mn1);
        m0 = mn0; m1 = mn1;

        float s0 = 0.f, s1 = 0.f;
#pragma unroll
        for (int ni = 0; ni < 8; ni++) {
            sacc[ni][0] = __expf(sacc[ni][0] - mn0);
            sacc[ni][1] = __expf(sacc[ni][1] - mn0);
            sacc[ni][2] = __expf(sacc[ni][2] - mn1);
            sacc[ni][3] = __expf(sacc[ni][3] - mn1);
            s0 += sacc[ni][0] + sacc[ni][1];
            s1 += sacc[ni][2] + sacc[ni][3];
        }
        s0 += __shfl_xor_sync(0xffffffffu, s0, 1);
        s0 += __shfl_xor_sync(0xffffffffu, s0, 2);
        s1 += __shfl_xor_sync(0xffffffffu, s1, 1);
        s1 += __shfl_xor_sync(0xffffffffu, s1, 2);
        l0 = l0 * cr0 + s0;
        l1 = l1 * cr1 + s1;

#pragma unroll
        for (int ni = 0; ni < 8; ni++) {
            oacc[ni][0] *= cr0; oacc[ni][1] *= cr0;
            oacc[ni][2] *= cr1; oacc[ni][3] *= cr1;
        }

        // ---- P fragments ----
        uint32_t ph[4][4], pl[4][4];
#pragma unroll
        for (int kt = 0; kt < 4; kt++) {
            const float* e0 = sacc[2 * kt];
            const float* e1 = sacc[2 * kt + 1];
            __nv_bfloat16 h00, l00, h01, l01, h02, l02, h03, l03;
            __nv_bfloat16 h10, l10, h11, l11, h12, l12, h13, l13;
            split1(e0[0], h00, l00); split1(e0[1], h01, l01);
            split1(e0[2], h02, l02); split1(e0[3], h03, l03);
            split1(e1[0], h10, l10); split1(e1[1], h11, l11);
            split1(e1[2], h12, l12); split1(e1[3], h13, l13);
            ph[kt][0] = pack_bf(h00, h01); ph[kt][1] = pack_bf(h02, h03);
            ph[kt][2] = pack_bf(h10, h11); ph[kt][3] = pack_bf(h12, h13);
            pl[kt][0] = pack_bf(l00, l01); pl[kt][1] = pack_bf(l02, l03);
            pl[kt][2] = pack_bf(l10, l11); pl[kt][3] = pack_bf(l12, l13);
        }

        // ---- PV: O += Ph*Vh + Pl*Vh + Ph*Vl ----
#pragma unroll
        for (int kt = 0; kt < 4; kt++) {
            uint32_t vf[4][4];
#pragma unroll
            for (int np = 0; np < 4; np++)
                ldsm_x4(vf[np][0], vf[np][1], vf[np][2], vf[np][3],
                        vhb + ((np * 16 + b_row4) * AT_KSTR + kt * 16 + b_koff4) * 2);
#pragma unroll
            for (int np = 0; np < 4; np++) {
                mma_bf16(oacc[2 * np],     ph[kt], vf[np][0], vf[np][1]);
                mma_bf16(oacc[2 * np + 1], ph[kt], vf[np][2], vf[np][3]);
            }
#pragma unroll
            for (int np = 0; np < 4; np++) {
                mma_bf16(oacc[2 * np],     pl[kt], vf[np][0], vf[np][1]);
                mma_bf16(oacc[2 * np + 1], pl[kt], vf[np][2], vf[np][3]);
            }
#pragma unroll
            for (int np = 0; np < 4; np++)
                ldsm_x4(vf[np][0], vf[np][1], vf[np][2], vf[np][3],
                        vlb + ((np * 16 + b_row4) * AT_KSTR + kt * 16 + b_koff4) * 2);
#pragma unroll
            for (int np = 0; np < 4; np++) {
                mma_bf16(oacc[2 * np],     ph[kt], vf[np][0], vf[np][1]);
                mma_bf16(oacc[2 * np + 1], ph[kt], vf[np][2], vf[np][3]);
            }
        }
    }

    // ---- epilogue: raw partials + (m, l) ----
#pragma unroll
    for (int hf = 0; hf < 2; hf++) {
        const int s = q0 + wid * 16 + gid + hf * 8;
        const size_t row = (size_t)bh * S_LEN + s;
#pragma unroll
        for (int ni = 0; ni < 8; ni++) {
            const int d = ni * 8 + tig * 2;
            *(float2*)&g_Opart[sp][row * DK + d] =
                make_float2(oacc[ni][hf * 2 + 0], oacc[ni][hf * 2 + 1]);
        }
        if (tig == 0)
            g_MLpart[sp][row] = make_float2(hf ? m1 : m0, hf ? l1 : l0);
    }
}

// combine the two split-K halves -> bf16 hi/lo attention output
__global__ __launch_bounds__(256) void attn_combine_kernel()
{
    size_t idx = ((size_t)blockIdx.x * 256 + threadIdx.x) * 4;
    size_t r = idx >> 6;
    int d = (int)(idx & 63);
    float2 ml0 = g_MLpart[0][r], ml1 = g_MLpart[1][r];
    float m = fmaxf(ml0.x, ml1.x);
    float c0 = __expf(ml0.x - m), c1 = __expf(ml1.x - m);
    float inv = 1.f / (c0 * ml0.y + c1 * ml1.y);
    float4 o0 = *(float4*)&g_Opart[0][idx];
    float4 o1 = *(float4*)&g_Opart[1][idx];
    float v0 = (c0 * o0.x + c1 * o1.x) * inv;
    float v1 = (c0 * o0.y + c1 * o1.y) * inv;
    float v2 = (c0 * o0.z + c1 * o1.z) * inv;
    float v3 = (c0 * o0.w + c1 * o1.w) * inv;

    int bz = (int)(r / (N_HEADS * S_LEN));
    int h  = (int)((r / S_LEN) % N_HEADS);
    int s  = (int)(r % S_LEN);
    size_t o = ((size_t)bz * S_LEN + s) * D_MODEL + h * DK + d;

    __nv_bfloat16 h0,l0,h1,l1,h2,l2,h3,l3;
    split1(v0,h0,l0); split1(v1,h1,l1); split1(v2,h2,l2); split1(v3,h3,l3);
    *(__nv_bfloat162*)&g_Oh[o]     = __nv_bfloat162(h0, h1);
    *(__nv_bfloat162*)&g_Oh[o + 2] = __nv_bfloat162(h2, h3);
    *(__nv_bfloat162*)&g_Ol[o]     = __nv_bfloat162(l0, l1);
    *(__nv_bfloat162*)&g_Ol[o + 2] = __nv_bfloat162(l2, l3);
}

// =====================================================================
extern "C" void kernel_launch(void* const* d_in, const int* in_sizes, int n_in,
                              void* d_out, int out_size)
{
    const float* q   = (const float*)d_in[0];
    const float* k   = (const float*)d_in[1];
    const float* v   = (const float*)d_in[2];
    const float* kpe = (const float*)d_in[3];
    const float* Wq  = (const float*)d_in[4];
    const float* bq  = (const float*)d_in[5];
    const float* Wk  = (const float*)d_in[6];
    const float* bk  = (const float*)d_in[7];
    const float* Wv  = (const float*)d_in[8];
    const float* bv  = (const float*)d_in[9];
    const float* Wo  = (const float*)d_in[10];
    const float* bo  = (const float*)d_in[11];
    float* out = (float*)d_out;

    cudaFuncSetAttribute(attn_mma_kernel, cudaFuncAttributeMaxDynamicSharedMemorySize,
                         ATTN_SMEM3);

    // prep: split inputs + weights to bf16 hi/lo
    dim3 gs(M_ROWS * D_MODEL / 1024, 3);
    split_qkv_kernel<<<gs, 256>>>(q, k, v);
    dim3 gw(32, 32, 4);
    splitW_kernel<<<gw, dim3(32, 8)>>>(Wq, Wk, Wv, Wo);

    // Q/K/V projections
    dim3 gp(D_MODEL / BN, M_ROWS / BM, 3);
    gemm_bf16_kernel<<<gp, 256>>>(0, kpe, bq, bk, bv, bo, out);

    // V transpose + split
    dim3 gv(DK / 32, S_LEN / 32, B_SIZE * N_HEADS);
    vtrans_kernel<<<gv, dim3(32, 8)>>>();

    // attention (tensor cores, register-resident P, 2-way split-K)
    dim3 ga(S_LEN / 128, N_HEADS, B_SIZE * 2);
    attn_mma_kernel<<<ga, 256, ATTN_SMEM3>>>();
    attn_combine_kernel<<<BHS * DK / 1024, 256>>>();

    // output projection
    dim3 go(D_MODEL / BN, M_ROWS / BM, 1);
    gemm_bf16_kernel<<<go, 256>>>(1, kpe, bq, bk, bv, bo, out);
}

// round 9
// speedup vs baseline: 1.5079x; 1.1760x over previous
#include <cuda_runtime.h>
#include <cuda_bf16.h>
#include <cstdint>

#define D_MODEL 1024
#define N_HEADS 16
#define DK      64
#define B_SIZE  2
#define S_LEN   2048
#define M_ROWS  (B_SIZE * S_LEN)   // 4096
#define BHS     (B_SIZE * N_HEADS * S_LEN)

// ---------------- scratch ----------------
__device__ float g_Vh[B_SIZE * N_HEADS * S_LEN * DK];          // V head-split fp32 (pre-transpose)

__device__ __nv_bfloat16 g_Ah[3][(size_t)M_ROWS * D_MODEL];
__device__ __nv_bfloat16 g_Al[3][(size_t)M_ROWS * D_MODEL];
__device__ __nv_bfloat16 g_Oh[(size_t)M_ROWS * D_MODEL];       // attn out hi
__device__ __nv_bfloat16 g_Ol[(size_t)M_ROWS * D_MODEL];       // attn out lo
__device__ __nv_bfloat16 g_Wth[4][(size_t)D_MODEL * D_MODEL];  // W^T hi [n][k]
__device__ __nv_bfloat16 g_Wtl[4][(size_t)D_MODEL * D_MODEL];  // W^T lo [n][k]

// attention operands (bf16 split)
__device__ __nv_bfloat16 g_Qbh[(size_t)M_ROWS * D_MODEL];      // [B,H,S,DK] hi, scaled 1/8
__device__ __nv_bfloat16 g_Qbl[(size_t)M_ROWS * D_MODEL];
__device__ __nv_bfloat16 g_Kbh[(size_t)M_ROWS * D_MODEL];      // [B,H,S,DK] hi (K + kpe)
__device__ __nv_bfloat16 g_Kbl[(size_t)M_ROWS * D_MODEL];
__device__ __nv_bfloat16 g_Vth[(size_t)M_ROWS * D_MODEL];      // [B,H,DK,S] hi (transposed)
__device__ __nv_bfloat16 g_Vtl[(size_t)M_ROWS * D_MODEL];

// split-K attention partials
__device__ float  g_Opart[2][(size_t)BHS * DK];                // raw (unnormalized) O
__device__ float2 g_MLpart[2][BHS];                            // (m, l) per row

// ======================= helpers =======================
__device__ __forceinline__ uint32_t smem_u32(const void* p) {
    uint32_t a;
    asm("{ .reg .u64 t; cvta.to.shared.u64 t, %1; cvt.u32.u64 %0, t; }" : "=r"(a) : "l"(p));
    return a;
}
__device__ __forceinline__ void cp16(uint32_t dst, const void* src) {
    asm volatile("cp.async.cg.shared.global [%0], [%1], 16;" :: "r"(dst), "l"(src));
}
__device__ __forceinline__ void ldsm_x4(uint32_t& r0, uint32_t& r1, uint32_t& r2, uint32_t& r3, uint32_t addr) {
    asm volatile("ldmatrix.sync.aligned.m8n8.x4.shared.b16 {%0,%1,%2,%3}, [%4];"
        : "=r"(r0), "=r"(r1), "=r"(r2), "=r"(r3) : "r"(addr));
}
__device__ __forceinline__ void ldsm_x2(uint32_t& r0, uint32_t& r1, uint32_t addr) {
    asm volatile("ldmatrix.sync.aligned.m8n8.x2.shared.b16 {%0,%1}, [%2];"
        : "=r"(r0), "=r"(r1) : "r"(addr));
}
__device__ __forceinline__ void mma_bf16(float* c, const uint32_t* a, uint32_t b0, uint32_t b1) {
    asm volatile("mma.sync.aligned.m16n8k16.row.col.f32.bf16.bf16.f32 "
        "{%0,%1,%2,%3}, {%4,%5,%6,%7}, {%8,%9}, {%0,%1,%2,%3};"
        : "+f"(c[0]), "+f"(c[1]), "+f"(c[2]), "+f"(c[3])
        : "r"(a[0]), "r"(a[1]), "r"(a[2]), "r"(a[3]), "r"(b0), "r"(b1));
}
__device__ __forceinline__ void split1(float x, __nv_bfloat16& h, __nv_bfloat16& l) {
    h = __float2bfloat16_rn(x);
    l = __float2bfloat16_rn(x - __bfloat162float(h));
}
__device__ __forceinline__ uint32_t pack_bf(__nv_bfloat16 a, __nv_bfloat16 b) {
    __nv_bfloat162 t(a, b);
    return *(uint32_t*)&t;
}

// ======================= split prep kernels =======================
__global__ __launch_bounds__(256) void split_qkv_kernel(
    const float* __restrict__ q, const float* __restrict__ k, const float* __restrict__ v)
{
    int z = blockIdx.y;
    const float* src = (z == 0) ? q : (z == 1) ? k : v;
    __nv_bfloat16* hi = g_Ah[z];
    __nv_bfloat16* lo = g_Al[z];
    size_t i = ((size_t)blockIdx.x * 256 + threadIdx.x) * 4;
    float4 a = *(const float4*)(src + i);
    __nv_bfloat16 h0,h1,h2,h3,l0,l1,l2,l3;
    split1(a.x,h0,l0); split1(a.y,h1,l1); split1(a.z,h2,l2); split1(a.w,h3,l3);
    *(__nv_bfloat162*)(hi+i)   = __nv_bfloat162(h0,h1);
    *(__nv_bfloat162*)(hi+i+2) = __nv_bfloat162(h2,h3);
    *(__nv_bfloat162*)(lo+i)   = __nv_bfloat162(l0,l1);
    *(__nv_bfloat162*)(lo+i+2) = __nv_bfloat162(l2,l3);
}

__global__ void splitW_kernel(
    const float* __restrict__ Wq, const float* __restrict__ Wk,
    const float* __restrict__ Wv, const float* __restrict__ Wo)
{
    __shared__ float sm[32][33];
    int z = blockIdx.z;
    const float* W = (z == 0) ? Wq : (z == 1) ? Wk : (z == 2) ? Wv : Wo;
    int n0 = blockIdx.x * 32, k0 = blockIdx.y * 32;
    int tx = threadIdx.x, ty = threadIdx.y;
#pragma unroll
    for (int i = 0; i < 4; i++)
        sm[ty + 8 * i][tx] = W[(size_t)(k0 + ty + 8 * i) * D_MODEL + n0 + tx];
    __syncthreads();
#pragma unroll
    for (int i = 0; i < 4; i++) {
        int c = ty + 8 * i;
        float vv = sm[tx][c];
        __nv_bfloat16 h, l;
        split1(vv, h, l);
        size_t o = (size_t)(n0 + c) * D_MODEL + k0 + tx;
        g_Wth[z][o] = h;
        g_Wtl[z][o] = l;
    }
}

// V transpose + split: g_Vh [B,H,S,DK] fp32 -> g_Vth/g_Vtl [B,H,DK,S] bf16
__global__ void vtrans_kernel()
{
    __shared__ float sm[32][33];
    int bh = blockIdx.z;
    int d0 = blockIdx.x * 32, s0 = blockIdx.y * 32;
    int tx = threadIdx.x, ty = threadIdx.y;
#pragma unroll
    for (int i = 0; i < 4; i++)
        sm[ty + 8 * i][tx] = g_Vh[((size_t)bh * S_LEN + s0 + ty + 8 * i) * DK + d0 + tx];
    __syncthreads();
#pragma unroll
    for (int i = 0; i < 4; i++) {
        int dl = ty + 8 * i;
        float vv = sm[tx][dl];
        __nv_bfloat16 h, l;
        split1(vv, h, l);
        size_t o = ((size_t)bh * DK + d0 + dl) * S_LEN + s0 + tx;
        g_Vth[o] = h;
        g_Vtl[o] = l;
    }
}

// ======================= fused-pass mma.sync bf16 split GEMM (no occupancy cap) =======================
// Per 32-wide K chunk: load Ah/Al/Wh/Wl tiles once, run Ah*Wh + Ah*Wl + Al*Wh. 32 steps.
#define BM 128
#define BN 128
#define KSTRIDE 40
#define G_TILE_B (128 * KSTRIDE * 2)     // 10240 bytes per tile
#define G_STAGE_B (4 * G_TILE_B)         // 40960 bytes per stage
#define GEMM_SMEM (2 * G_STAGE_B)        // 81920 bytes

__global__ __launch_bounds__(256)
void gemm_bf16_kernel(int mode, const float* __restrict__ kpe,
                      const float* __restrict__ bq, const float* __restrict__ bk,
                      const float* __restrict__ bv, const float* __restrict__ bo,
                      float* __restrict__ out_final)
{
    extern __shared__ char sgem[];
    const uint32_t sbase = smem_u32(sgem);

    const int z = blockIdx.z;
    const __nv_bfloat16 *Ahp, *Alp, *Whp, *Wlp;
    const float* bias;
    if (mode == 0) {
        Ahp = g_Ah[z]; Alp = g_Al[z]; Whp = g_Wth[z]; Wlp = g_Wtl[z];
        bias = (z == 0) ? bq : (z == 1) ? bk : bv;
    } else {
        Ahp = g_Oh; Alp = g_Ol; Whp = g_Wth[3]; Wlp = g_Wtl[3];
        bias = bo;
    }

    const int m0 = blockIdx.y * BM;
    const int n0 = blockIdx.x * BN;
    const int tid = threadIdx.x;
    const int wid = tid >> 5, lane = tid & 31;
    const int wm = wid & 1, wn = wid >> 1;

    const int lrow = tid >> 1, lcp = tid & 1;

    auto load_chunk = [&](int kc, int buf) {
        const size_t ga = (size_t)(m0 + lrow) * D_MODEL + kc * 32 + lcp * 16;
        const size_t gb = (size_t)(n0 + lrow) * D_MODEL + kc * 32 + lcp * 16;
        const uint32_t so = sbase + buf * G_STAGE_B + (lrow * KSTRIDE + lcp * 16) * 2;
        cp16(so,                     Ahp + ga); cp16(so + 16,                Ahp + ga + 8);
        cp16(so + G_TILE_B,          Alp + ga); cp16(so + G_TILE_B + 16,     Alp + ga + 8);
        cp16(so + 2 * G_TILE_B,      Whp + gb); cp16(so + 2 * G_TILE_B + 16, Whp + gb + 8);
        cp16(so + 3 * G_TILE_B,      Wlp + gb); cp16(so + 3 * G_TILE_B + 16, Wlp + gb + 8);
        asm volatile("cp.async.commit_group;" ::: "memory");
    };

    float acc[4][4][4];
#pragma unroll
    for (int i = 0; i < 4; i++)
#pragma unroll
        for (int j = 0; j < 4; j++)
#pragma unroll
            for (int c = 0; c < 4; c++) acc[i][j][c] = 0.f;

    load_chunk(0, 0);
    load_chunk(1, 1);

    const int a_row = (lane & 15), a_koff = (lane >> 4) * 8;
    const int b_row = (lane & 7),  b_koff = ((lane >> 3) & 1) * 8;

    for (int c = 0; c < 32; c++) {
        const int buf = c & 1;
        if (c < 31) asm volatile("cp.async.wait_group 1;" ::: "memory");
        else        asm volatile("cp.async.wait_group 0;" ::: "memory");
        __syncthreads();

        const uint32_t st = sbase + buf * G_STAGE_B;
#pragma unroll
        for (int k16 = 0; k16 < 2; k16++) {
            uint32_t a[4][4], bh[4][2];
            // A = Ah, B = Wh
#pragma unroll
            for (int mi = 0; mi < 4; mi++)
                ldsm_x4(a[mi][0], a[mi][1], a[mi][2], a[mi][3],
                        st + ((wm * 64 + mi * 16 + a_row) * KSTRIDE + k16 * 16 + a_koff) * 2);
#pragma unroll
            for (int ni = 0; ni < 4; ni++)
                ldsm_x2(bh[ni][0], bh[ni][1],
                        st + 2 * G_TILE_B + ((wn * 32 + ni * 8 + b_row) * KSTRIDE + k16 * 16 + b_koff) * 2);
#pragma unroll
            for (int ni = 0; ni < 4; ni++)
#pragma unroll
                for (int mi = 0; mi < 4; mi++)
                    mma_bf16(acc[mi][ni], a[mi], bh[ni][0], bh[ni][1]);
            // B = Wl (short-lived), A still Ah
            {
                uint32_t bl[4][2];
#pragma unroll
                for (int ni = 0; ni < 4; ni++)
                    ldsm_x2(bl[ni][0], bl[ni][1],
                            st + 3 * G_TILE_B + ((wn * 32 + ni * 8 + b_row) * KSTRIDE + k16 * 16 + b_koff) * 2);
#pragma unroll
                for (int ni = 0; ni < 4; ni++)
#pragma unroll
                    for (int mi = 0; mi < 4; mi++)
                        mma_bf16(acc[mi][ni], a[mi], bl[ni][0], bl[ni][1]);
            }
            // A = Al (overwrite), B = Wh (still live)
#pragma unroll
            for (int mi = 0; mi < 4; mi++)
                ldsm_x4(a[mi][0], a[mi][1], a[mi][2], a[mi][3],
                        st + G_TILE_B + ((wm * 64 + mi * 16 + a_row) * KSTRIDE + k16 * 16 + a_koff) * 2);
#pragma unroll
            for (int ni = 0; ni < 4; ni++)
#pragma unroll
                for (int mi = 0; mi < 4; mi++)
                    mma_bf16(acc[mi][ni], a[mi], bh[ni][0], bh[ni][1]);
        }
        __syncthreads();
        if (c + 2 < 32) load_chunk(c + 2, buf);
    }

    const int gid = lane >> 2, tig = lane & 3;
#pragma unroll
    for (int mi = 0; mi < 4; mi++) {
#pragma unroll
        for (int half = 0; half < 2; half++) {
            const int m = m0 + wm * 64 + mi * 16 + gid + half * 8;
            const int bb = m >> 11, s = m & 2047;
#pragma unroll
            for (int ni = 0; ni < 4; ni++) {
                const int n = n0 + wn * 32 + ni * 8 + tig * 2;
                float c0 = acc[mi][ni][half * 2 + 0] + bias[n];
                float c1 = acc[mi][ni][half * 2 + 1] + bias[n + 1];
                if (mode == 0) {
                    const int h = n >> 6, d = n & 63;
                    size_t o = (((size_t)bb * N_HEADS + h) * S_LEN + s) * DK + d;
                    if (z == 0) {
                        __nv_bfloat16 h0,l0,h1,l1;
                        split1(c0 * 0.125f, h0, l0);
                        split1(c1 * 0.125f, h1, l1);
                        *(__nv_bfloat162*)&g_Qbh[o] = __nv_bfloat162(h0, h1);
                        *(__nv_bfloat162*)&g_Qbl[o] = __nv_bfloat162(l0, l1);
                    } else if (z == 1) {
                        c0 += kpe[((size_t)h * DK + d) * S_LEN + s];
                        c1 += kpe[((size_t)h * DK + d + 1) * S_LEN + s];
                        __nv_bfloat16 h0,l0,h1,l1;
                        split1(c0, h0, l0);
                        split1(c1, h1, l1);
                        *(__nv_bfloat162*)&g_Kbh[o] = __nv_bfloat162(h0, h1);
                        *(__nv_bfloat162*)&g_Kbl[o] = __nv_bfloat162(l0, l1);
                    } else {
                        *(float2*)&g_Vh[o] = make_float2(c0, c1);
                    }
                } else {
                    *(float2*)&out_final[(size_t)m * D_MODEL + n] = make_float2(c0, c1);
                }
            }
        }
    }
}

// ======================= register-resident flash attention, 2-way split-K =======================
#define AT_KSTR 72
#define AQ_OFF  0
#define AKH_OFF 18432
#define AKL_OFF (AKH_OFF + 2 * 9216)
#define AVH_OFF (AKL_OFF + 2 * 9216)
#define AVL_OFF (AVH_OFF + 2 * 9216)
#define ATTN_SMEM3 (AVL_OFF + 2 * 9216)   // 92160 B
#define SPLIT_TILES 16                    // 16 tiles of 64 keys per split

__global__ __launch_bounds__(256)
void attn_mma_kernel()
{
    extern __shared__ char smc[];
    const uint32_t base = smem_u32(smc);

    const int tid = threadIdx.x;
    const int wid = tid >> 5, lane = tid & 31;
    const int q0 = blockIdx.x * 128;
    const int h = blockIdx.y;
    const int bz = blockIdx.z >> 1, sp = blockIdx.z & 1;
    const int bh = bz * N_HEADS + h;
    const int T0 = sp * SPLIT_TILES;

    const int a_row = (lane & 15), a_koff = (lane >> 4) * 8;
    const int b_row4 = (lane & 7) + ((lane >> 4) << 3);
    const int b_koff4 = ((lane >> 3) & 1) * 8;
    const int gid = lane >> 2, tig = lane & 3;

    // ---- load Q fragments ----
    uint32_t qh[4][4], ql[4][4];
    for (int r = 0; r < 2; r++) {
        const __nv_bfloat16* Qg = r ? g_Qbl : g_Qbh;
#pragma unroll
        for (int it = 0; it < 4; it++) {
            int idx = tid + it * 256;
            int row = idx >> 3, cp = idx & 7;
            cp16(base + AQ_OFF + (row * AT_KSTR + cp * 8) * 2,
                 Qg + ((size_t)bh * S_LEN + q0 + row) * DK + cp * 8);
        }
        asm volatile("cp.async.commit_group;" ::: "memory");
        asm volatile("cp.async.wait_group 0;" ::: "memory");
        __syncthreads();
#pragma unroll
        for (int k16 = 0; k16 < 4; k16++) {
            uint32_t* f = r ? ql[k16] : qh[k16];
            ldsm_x4(f[0], f[1], f[2], f[3],
                    base + AQ_OFF + ((wid * 16 + a_row) * AT_KSTR + k16 * 16 + a_koff) * 2);
        }
        __syncthreads();
    }

    auto load_kv = [&](int T, int bufx) {
        const int t0 = T * 64;
        const __nv_bfloat16* srcs[4] = { g_Kbh, g_Kbl, g_Vth, g_Vtl };
        const uint32_t dsts[4] = { AKH_OFF, AKL_OFF, AVH_OFF, AVL_OFF };
#pragma unroll
        for (int arr = 0; arr < 4; arr++)
#pragma unroll
            for (int hf = 0; hf < 2; hf++) {
                int rem = tid + hf * 256;
                int row = rem >> 3, cp = rem & 7;
                const __nv_bfloat16* src;
                if (arr < 2) src = srcs[arr] + ((size_t)bh * S_LEN + t0 + row) * DK + cp * 8;
                else         src = srcs[arr] + ((size_t)bh * DK + row) * S_LEN + t0 + cp * 8;
                cp16(base + dsts[arr] + bufx * 9216 + (row * AT_KSTR + cp * 8) * 2, src);
            }
        asm volatile("cp.async.commit_group;" ::: "memory");
    };

    float oacc[8][4];
#pragma unroll
    for (int ni = 0; ni < 8; ni++)
#pragma unroll
        for (int c = 0; c < 4; c++) oacc[ni][c] = 0.f;
    float m0 = -1e30f, m1 = -1e30f, l0 = 0.f, l1 = 0.f;

    load_kv(T0, 0);

#pragma unroll 1
    for (int Ti = 0; Ti < SPLIT_TILES; Ti++) {
        const int buf = Ti & 1;
        asm volatile("cp.async.wait_group 0;" ::: "memory");
        __syncthreads();
        if (Ti + 1 < SPLIT_TILES) load_kv(T0 + Ti + 1, buf ^ 1);

        const uint32_t khb = base + AKH_OFF + buf * 9216;
        const uint32_t klb = base + AKL_OFF + buf * 9216;
        const uint32_t vhb = base + AVH_OFF + buf * 9216;
        const uint32_t vlb = base + AVL_OFF + buf * 9216;

        // ---- QK^T: S = Qh*Kh + Qh*Kl + Ql*Kh ----
        float sacc[8][4];
#pragma unroll
        for (int ni = 0; ni < 8; ni++)
#pragma unroll
            for (int c = 0; c < 4; c++) sacc[ni][c] = 0.f;

#pragma unroll
        for (int kd = 0; kd < 4; kd++) {
            uint32_t kf[4][4];
#pragma unroll
            for (int np = 0; np < 4; np++)
                ldsm_x4(kf[np][0], kf[np][1], kf[np][2], kf[np][3],
                        khb + ((np * 16 + b_row4) * AT_KSTR + kd * 16 + b_koff4) * 2);
#pragma unroll
            for (int np = 0; np < 4; np++) {
                mma_bf16(sacc[2 * np],     qh[kd], kf[np][0], kf[np][1]);
                mma_bf16(sacc[2 * np + 1], qh[kd], kf[np][2], kf[np][3]);
            }
#pragma unroll
            for (int np = 0; np < 4; np++) {
                mma_bf16(sacc[2 * np],     ql[kd], kf[np][0], kf[np][1]);
                mma_bf16(sacc[2 * np + 1], ql[kd], kf[np][2], kf[np][3]);
            }
#pragma unroll
            for (int np = 0; np < 4; np++)
                ldsm_x4(kf[np][0], kf[np][1], kf[np][2], kf[np][3],
                        klb + ((np * 16 + b_row4) * AT_KSTR + kd * 16 + b_koff4) * 2);
#pragma unroll
            for (int np = 0; np < 4; np++) {
                mma_bf16(sacc[2 * np],     qh[kd], kf[np][0], kf[np][1]);
                mma_bf16(sacc[2 * np + 1], qh[kd], kf[np][2], kf[np][3]);
            }
        }

        // ---- register softmax ----
        float mx0 = -1e30f, mx1 = -1e30f;
#pragma unroll
        for (int ni = 0; ni < 8; ni++) {
            mx0 = fmaxf(mx0, fmaxf(sacc[ni][0], sacc[ni][1]));
            mx1 = fmaxf(mx1, fmaxf(sacc[ni][2], sacc[ni][3]));
        }
        mx0 = fmaxf(mx0, __shfl_xor_sync(0xffffffffu, mx0, 1));
        mx0 = fmaxf(mx0, __shfl_xor_sync(0xffffffffu, mx0, 2));
        mx1 = fmaxf(mx1, __shfl_xor_sync(0xffffffffu, mx1, 1));
        mx1 = fmaxf(mx1, __shfl_xor_sync(0xffffffffu, mx1, 2));

        const float mn0 = fmaxf(m0, mx0), mn1 = fmaxf(m1, mx1);
        const float cr0 = __expf(m0 - mn0), cr1 = __expf(m1 - mn1);
        m0 = mn0; m1 = mn1;

        float s0 = 0.f, s1 = 0.f;
#pragma unroll
        for (int ni = 0; ni < 8; ni++) {
            sacc[ni][0] = __expf(sacc[ni][0] - mn0);
            sacc[ni][1] = __expf(sacc[ni][1] - mn0);
            sacc[ni][2] = __expf(sacc[ni][2] - mn1);
            sacc[ni][3] = __expf(sacc[ni][3] - mn1);
            s0 += sacc[ni][0] + sacc[ni][1];
            s1 += sacc[ni][2] + sacc[ni][3];
        }
        s0 += __shfl_xor_sync(0xffffffffu, s0, 1);
        s0 += __shfl_xor_sync(0xffffffffu, s0, 2);
        s1 += __shfl_xor_sync(0xffffffffu, s1, 1);
        s1 += __shfl_xor_sync(0xffffffffu, s1, 2);
        l0 = l0 * cr0 + s0;
        l1 = l1 * cr1 + s1;

#pragma unroll
        for (int ni = 0; ni < 8; ni++) {
            oacc[ni][0] *= cr0; oacc[ni][1] *= cr0;
            oacc[ni][2] *= cr1; oacc[ni][3] *= cr1;
        }

        // ---- P fragments ----
        uint32_t ph[4][4], pl[4][4];
#pragma unroll
        for (int kt = 0; kt < 4; kt++) {
            const float* e0 = sacc[2 * kt];
            const float* e1 = sacc[2 * kt + 1];
            __nv_bfloat16 h00, l00, h01, l01, h02, l02, h03, l03;
            __nv_bfloat16 h10, l10, h11, l11, h12, l12, h13, l13;
            split1(e0[0], h00, l00); split1(e0[1], h01, l01);
            split1(e0[2], h02, l02); split1(e0[3], h03, l03);
            split1(e1[0], h10, l10); split1(e1[1], h11, l11);
            split1(e1[2], h12, l12); split1(e1[3], h13, l13);
            ph[kt][0] = pack_bf(h00, h01); ph[kt][1] = pack_bf(h02, h03);
            ph[kt][2] = pack_bf(h10, h11); ph[kt][3] = pack_bf(h12, h13);
            pl[kt][0] = pack_bf(l00, l01); pl[kt][1] = pack_bf(l02, l03);
            pl[kt][2] = pack_bf(l10, l11); pl[kt][3] = pack_bf(l12, l13);
        }

        // ---- PV: O += Ph*Vh + Pl*Vh + Ph*Vl ----
#pragma unroll
        for (int kt = 0; kt < 4; kt++) {
            uint32_t vf[4][4];
#pragma unroll
            for (int np = 0; np < 4; np++)
                ldsm_x4(vf[np][0], vf[np][1], vf[np][2], vf[np][3],
                        vhb + ((np * 16 + b_row4) * AT_KSTR + kt * 16 + b_koff4) * 2);
#pragma unroll
            for (int np = 0; np < 4; np++) {
                mma_bf16(oacc[2 * np],     ph[kt], vf[np][0], vf[np][1]);
                mma_bf16(oacc[2 * np + 1], ph[kt], vf[np][2], vf[np][3]);
            }
#pragma unroll
            for (int np = 0; np < 4; np++) {
                mma_bf16(oacc[2 * np],     pl[kt], vf[np][0], vf[np][1]);
                mma_bf16(oacc[2 * np + 1], pl[kt], vf[np][2], vf[np][3]);
            }
#pragma unroll
            for (int np = 0; np < 4; np++)
                ldsm_x4(vf[np][0], vf[np][1], vf[np][2], vf[np][3],
                        vlb + ((np * 16 + b_row4) * AT_KSTR + kt * 16 + b_koff4) * 2);
#pragma unroll
            for (int np = 0; np < 4; np++) {
                mma_bf16(oacc[2 * np],     ph[kt], vf[np][0], vf[np][1]);
                mma_bf16(oacc[2 * np + 1], ph[kt], vf[np][2], vf[np][3]);
            }
        }
    }

    // ---- epilogue: raw partials + (m, l) ----
#pragma unroll
    for (int hf = 0; hf < 2; hf++) {
        const int s = q0 + wid * 16 + gid + hf * 8;
        const size_t row = (size_t)bh * S_LEN + s;
#pragma unroll
        for (int ni = 0; ni < 8; ni++) {
            const int d = ni * 8 + tig * 2;
            *(float2*)&g_Opart[sp][row * DK + d] =
                make_float2(oacc[ni][hf * 2 + 0], oacc[ni][hf * 2 + 1]);
        }
        if (tig == 0)
            g_MLpart[sp][row] = make_float2(hf ? m1 : m0, hf ? l1 : l0);
    }
}

// combine the two split-K halves -> bf16 hi/lo attention output
__global__ __launch_bounds__(256) void attn_combine_kernel()
{
    size_t idx = ((size_t)blockIdx.x * 256 + threadIdx.x) * 4;
    size_t r = idx >> 6;
    int d = (int)(idx & 63);
    float2 ml0 = g_MLpart[0][r], ml1 = g_MLpart[1][r];
    float m = fmaxf(ml0.x, ml1.x);
    float c0 = __expf(ml0.x - m), c1 = __expf(ml1.x - m);
    float inv = 1.f / (c0 * ml0.y + c1 * ml1.y);
    float4 o0 = *(float4*)&g_Opart[0][idx];
    float4 o1 = *(float4*)&g_Opart[1][idx];
    float v0 = (c0 * o0.x + c1 * o1.x) * inv;
    float v1 = (c0 * o0.y + c1 * o1.y) * inv;
    float v2 = (c0 * o0.z + c1 * o1.z) * inv;
    float v3 = (c0 * o0.w + c1 * o1.w) * inv;

    int bz = (int)(r / (N_HEADS * S_LEN));
    int h  = (int)((r / S_LEN) % N_HEADS);
    int s  = (int)(r % S_LEN);
    size_t o = ((size_t)bz * S_LEN + s) * D_MODEL + h * DK + d;

    __nv_bfloat16 h0,l0,h1,l1,h2,l2,h3,l3;
    split1(v0,h0,l0); split1(v1,h1,l1); split1(v2,h2,l2); split1(v3,h3,l3);
    *(__nv_bfloat162*)&g_Oh[o]     = __nv_bfloat162(h0, h1);
    *(__nv_bfloat162*)&g_Oh[o + 2] = __nv_bfloat162(h2, h3);
    *(__nv_bfloat162*)&g_Ol[o]     = __nv_bfloat162(l0, l1);
    *(__nv_bfloat162*)&g_Ol[o + 2] = __nv_bfloat162(l2, l3);
}

// =====================================================================
extern "C" void kernel_launch(void* const* d_in, const int* in_sizes, int n_in,
                              void* d_out, int out_size)
{
    const float* q   = (const float*)d_in[0];
    const float* k   = (const float*)d_in[1];
    const float* v   = (const float*)d_in[2];
    const float* kpe = (const float*)d_in[3];
    const float* Wq  = (const float*)d_in[4];
    const float* bq  = (const float*)d_in[5];
    const float* Wk  = (const float*)d_in[6];
    const float* bk  = (const float*)d_in[7];
    const float* Wv  = (const float*)d_in[8];
    const float* bv  = (const float*)d_in[9];
    const float* Wo  = (const float*)d_in[10];
    const float* bo  = (const float*)d_in[11];
    float* out = (float*)d_out;

    cudaFuncSetAttribute(attn_mma_kernel, cudaFuncAttributeMaxDynamicSharedMemorySize,
                         ATTN_SMEM3);
    cudaFuncSetAttribute(gemm_bf16_kernel, cudaFuncAttributeMaxDynamicSharedMemorySize,
                         GEMM_SMEM);

    // prep: split inputs + weights to bf16 hi/lo
    dim3 gs(M_ROWS * D_MODEL / 1024, 3);
    split_qkv_kernel<<<gs, 256>>>(q, k, v);
    dim3 gw(32, 32, 4);
    splitW_kernel<<<gw, dim3(32, 8)>>>(Wq, Wk, Wv, Wo);

    // Q/K/V projections
    dim3 gp(D_MODEL / BN, M_ROWS / BM, 3);
    gemm_bf16_kernel<<<gp, 256, GEMM_SMEM>>>(0, kpe, bq, bk, bv, bo, out);

    // V transpose + split
    dim3 gv(DK / 32, S_LEN / 32, B_SIZE * N_HEADS);
    vtrans_kernel<<<gv, dim3(32, 8)>>>();

    // attention (tensor cores, register-resident P, 2-way split-K)
    dim3 ga(S_LEN / 128, N_HEADS, B_SIZE * 2);
    attn_mma_kernel<<<ga, 256, ATTN_SMEM3>>>();
    attn_combine_kernel<<<BHS * DK / 1024, 256>>>();

    // output projection
    dim3 go(D_MODEL / BN, M_ROWS / BM, 1);
    gemm_bf16_kernel<<<go, 256, GEMM_SMEM>>>(1, kpe, bq, bk, bv, bo, out);
}

// round 10
// speedup vs baseline: 2.0626x; 1.3679x over previous
#include <cuda_runtime.h>
#include <cuda_bf16.h>
#include <cuda_fp16.h>
#include <cstdint>

#define D_MODEL 1024
#define N_HEADS 16
#define DK      64
#define B_SIZE  2
#define S_LEN   2048
#define M_ROWS  (B_SIZE * S_LEN)   // 4096
#define BHS     (B_SIZE * N_HEADS * S_LEN)

// ---------------- scratch ----------------
__device__ float g_Vh[B_SIZE * N_HEADS * S_LEN * DK];          // V head-split fp32 (pre-transpose)

__device__ __nv_bfloat16 g_Ah[3][(size_t)M_ROWS * D_MODEL];
__device__ __nv_bfloat16 g_Al[3][(size_t)M_ROWS * D_MODEL];
__device__ __nv_bfloat16 g_Oh[(size_t)M_ROWS * D_MODEL];       // attn out hi
__device__ __nv_bfloat16 g_Ol[(size_t)M_ROWS * D_MODEL];       // attn out lo
__device__ __nv_bfloat16 g_Wth[4][(size_t)D_MODEL * D_MODEL];  // W^T hi [n][k]
__device__ __nv_bfloat16 g_Wtl[4][(size_t)D_MODEL * D_MODEL];  // W^T lo [n][k]

// attention operands (fp16, single precision pass)
__device__ __half g_Qf[(size_t)M_ROWS * D_MODEL];              // [B,H,S,DK], scaled 1/8
__device__ __half g_Kf[(size_t)M_ROWS * D_MODEL];              // [B,H,S,DK] (K + kpe)
__device__ __half g_Vtf[(size_t)M_ROWS * D_MODEL];             // [B,H,DK,S] (transposed)

// split-K attention partials
__device__ float  g_Opart[2][(size_t)BHS * DK];                // raw (unnormalized) O
__device__ float2 g_MLpart[2][BHS];                            // (m, l) per row

// ======================= helpers =======================
__device__ __forceinline__ uint32_t smem_u32(const void* p) {
    uint32_t a;
    asm("{ .reg .u64 t; cvta.to.shared.u64 t, %1; cvt.u32.u64 %0, t; }" : "=r"(a) : "l"(p));
    return a;
}
__device__ __forceinline__ void cp16(uint32_t dst, const void* src) {
    asm volatile("cp.async.cg.shared.global [%0], [%1], 16;" :: "r"(dst), "l"(src));
}
__device__ __forceinline__ void ldsm_x4(uint32_t& r0, uint32_t& r1, uint32_t& r2, uint32_t& r3, uint32_t addr) {
    asm volatile("ldmatrix.sync.aligned.m8n8.x4.shared.b16 {%0,%1,%2,%3}, [%4];"
        : "=r"(r0), "=r"(r1), "=r"(r2), "=r"(r3) : "r"(addr));
}
__device__ __forceinline__ void ldsm_x2(uint32_t& r0, uint32_t& r1, uint32_t addr) {
    asm volatile("ldmatrix.sync.aligned.m8n8.x2.shared.b16 {%0,%1}, [%2];"
        : "=r"(r0), "=r"(r1) : "r"(addr));
}
__device__ __forceinline__ void mma_bf16(float* c, const uint32_t* a, uint32_t b0, uint32_t b1) {
    asm volatile("mma.sync.aligned.m16n8k16.row.col.f32.bf16.bf16.f32 "
        "{%0,%1,%2,%3}, {%4,%5,%6,%7}, {%8,%9}, {%0,%1,%2,%3};"
        : "+f"(c[0]), "+f"(c[1]), "+f"(c[2]), "+f"(c[3])
        : "r"(a[0]), "r"(a[1]), "r"(a[2]), "r"(a[3]), "r"(b0), "r"(b1));
}
__device__ __forceinline__ void mma_f16(float* c, const uint32_t* a, uint32_t b0, uint32_t b1) {
    asm volatile("mma.sync.aligned.m16n8k16.row.col.f32.f16.f16.f32 "
        "{%0,%1,%2,%3}, {%4,%5,%6,%7}, {%8,%9}, {%0,%1,%2,%3};"
        : "+f"(c[0]), "+f"(c[1]), "+f"(c[2]), "+f"(c[3])
        : "r"(a[0]), "r"(a[1]), "r"(a[2]), "r"(a[3]), "r"(b0), "r"(b1));
}
__device__ __forceinline__ void split1(float x, __nv_bfloat16& h, __nv_bfloat16& l) {
    h = __float2bfloat16_rn(x);
    l = __float2bfloat16_rn(x - __bfloat162float(h));
}
__device__ __forceinline__ uint32_t pack_h2(float a, float b) {
    __half2 t = __floats2half2_rn(a, b);
    return *(uint32_t*)&t;
}

// ======================= split prep kernels =======================
__global__ __launch_bounds__(256) void split_qkv_kernel(
    const float* __restrict__ q, const float* __restrict__ k, const float* __restrict__ v)
{
    int z = blockIdx.y;
    const float* src = (z == 0) ? q : (z == 1) ? k : v;
    __nv_bfloat16* hi = g_Ah[z];
    __nv_bfloat16* lo = g_Al[z];
    size_t i = ((size_t)blockIdx.x * 256 + threadIdx.x) * 4;
    float4 a = *(const float4*)(src + i);
    __nv_bfloat16 h0,h1,h2,h3,l0,l1,l2,l3;
    split1(a.x,h0,l0); split1(a.y,h1,l1); split1(a.z,h2,l2); split1(a.w,h3,l3);
    *(__nv_bfloat162*)(hi+i)   = __nv_bfloat162(h0,h1);
    *(__nv_bfloat162*)(hi+i+2) = __nv_bfloat162(h2,h3);
    *(__nv_bfloat162*)(lo+i)   = __nv_bfloat162(l0,l1);
    *(__nv_bfloat162*)(lo+i+2) = __nv_bfloat162(l2,l3);
}

__global__ void splitW_kernel(
    const float* __restrict__ Wq, const float* __restrict__ Wk,
    const float* __restrict__ Wv, const float* __restrict__ Wo)
{
    __shared__ float sm[32][33];
    int z = blockIdx.z;
    const float* W = (z == 0) ? Wq : (z == 1) ? Wk : (z == 2) ? Wv : Wo;
    int n0 = blockIdx.x * 32, k0 = blockIdx.y * 32;
    int tx = threadIdx.x, ty = threadIdx.y;
#pragma unroll
    for (int i = 0; i < 4; i++)
        sm[ty + 8 * i][tx] = W[(size_t)(k0 + ty + 8 * i) * D_MODEL + n0 + tx];
    __syncthreads();
#pragma unroll
    for (int i = 0; i < 4; i++) {
        int c = ty + 8 * i;
        float vv = sm[tx][c];
        __nv_bfloat16 h, l;
        split1(vv, h, l);
        size_t o = (size_t)(n0 + c) * D_MODEL + k0 + tx;
        g_Wth[z][o] = h;
        g_Wtl[z][o] = l;
    }
}

// V transpose: g_Vh [B,H,S,DK] fp32 -> g_Vtf [B,H,DK,S] fp16
__global__ void vtrans_kernel()
{
    __shared__ float sm[32][33];
    int bh = blockIdx.z;
    int d0 = blockIdx.x * 32, s0 = blockIdx.y * 32;
    int tx = threadIdx.x, ty = threadIdx.y;
#pragma unroll
    for (int i = 0; i < 4; i++)
        sm[ty + 8 * i][tx] = g_Vh[((size_t)bh * S_LEN + s0 + ty + 8 * i) * DK + d0 + tx];
    __syncthreads();
#pragma unroll
    for (int i = 0; i < 4; i++) {
        int dl = ty + 8 * i;
        g_Vtf[((size_t)bh * DK + d0 + dl) * S_LEN + s0 + tx] = __float2half_rn(sm[tx][dl]);
    }
}

// ======================= fused-pass mma.sync bf16 split GEMM =======================
#define BM 128
#define BN 128
#define KSTRIDE 40
#define G_TILE_B (128 * KSTRIDE * 2)
#define G_STAGE_B (4 * G_TILE_B)
#define GEMM_SMEM (2 * G_STAGE_B)

__global__ __launch_bounds__(256)
void gemm_bf16_kernel(int mode, const float* __restrict__ kpe,
                      const float* __restrict__ bq, const float* __restrict__ bk,
                      const float* __restrict__ bv, const float* __restrict__ bo,
                      float* __restrict__ out_final)
{
    extern __shared__ char sgem[];
    const uint32_t sbase = smem_u32(sgem);

    const int z = blockIdx.z;
    const __nv_bfloat16 *Ahp, *Alp, *Whp, *Wlp;
    const float* bias;
    if (mode == 0) {
        Ahp = g_Ah[z]; Alp = g_Al[z]; Whp = g_Wth[z]; Wlp = g_Wtl[z];
        bias = (z == 0) ? bq : (z == 1) ? bk : bv;
    } else {
        Ahp = g_Oh; Alp = g_Ol; Whp = g_Wth[3]; Wlp = g_Wtl[3];
        bias = bo;
    }

    const int m0 = blockIdx.y * BM;
    const int n0 = blockIdx.x * BN;
    const int tid = threadIdx.x;
    const int wid = tid >> 5, lane = tid & 31;
    const int wm = wid & 1, wn = wid >> 1;

    const int lrow = tid >> 1, lcp = tid & 1;

    auto load_chunk = [&](int kc, int buf) {
        const size_t ga = (size_t)(m0 + lrow) * D_MODEL + kc * 32 + lcp * 16;
        const size_t gb = (size_t)(n0 + lrow) * D_MODEL + kc * 32 + lcp * 16;
        const uint32_t so = sbase + buf * G_STAGE_B + (lrow * KSTRIDE + lcp * 16) * 2;
        cp16(so,                     Ahp + ga); cp16(so + 16,                Ahp + ga + 8);
        cp16(so + G_TILE_B,          Alp + ga); cp16(so + G_TILE_B + 16,     Alp + ga + 8);
        cp16(so + 2 * G_TILE_B,      Whp + gb); cp16(so + 2 * G_TILE_B + 16, Whp + gb + 8);
        cp16(so + 3 * G_TILE_B,      Wlp + gb); cp16(so + 3 * G_TILE_B + 16, Wlp + gb + 8);
        asm volatile("cp.async.commit_group;" ::: "memory");
    };

    float acc[4][4][4];
#pragma unroll
    for (int i = 0; i < 4; i++)
#pragma unroll
        for (int j = 0; j < 4; j++)
#pragma unroll
            for (int c = 0; c < 4; c++) acc[i][j][c] = 0.f;

    load_chunk(0, 0);
    load_chunk(1, 1);

    const int a_row = (lane & 15), a_koff = (lane >> 4) * 8;
    const int b_row = (lane & 7),  b_koff = ((lane >> 3) & 1) * 8;

    for (int c = 0; c < 32; c++) {
        const int buf = c & 1;
        if (c < 31) asm volatile("cp.async.wait_group 1;" ::: "memory");
        else        asm volatile("cp.async.wait_group 0;" ::: "memory");
        __syncthreads();

        const uint32_t st = sbase + buf * G_STAGE_B;
#pragma unroll
        for (int k16 = 0; k16 < 2; k16++) {
            uint32_t a[4][4], bh[4][2];
#pragma unroll
            for (int mi = 0; mi < 4; mi++)
                ldsm_x4(a[mi][0], a[mi][1], a[mi][2], a[mi][3],
                        st + ((wm * 64 + mi * 16 + a_row) * KSTRIDE + k16 * 16 + a_koff) * 2);
#pragma unroll
            for (int ni = 0; ni < 4; ni++)
                ldsm_x2(bh[ni][0], bh[ni][1],
                        st + 2 * G_TILE_B + ((wn * 32 + ni * 8 + b_row) * KSTRIDE + k16 * 16 + b_koff) * 2);
#pragma unroll
            for (int ni = 0; ni < 4; ni++)
#pragma unroll
                for (int mi = 0; mi < 4; mi++)
                    mma_bf16(acc[mi][ni], a[mi], bh[ni][0], bh[ni][1]);
            {
                uint32_t bl[4][2];
#pragma unroll
                for (int ni = 0; ni < 4; ni++)
                    ldsm_x2(bl[ni][0], bl[ni][1],
                            st + 3 * G_TILE_B + ((wn * 32 + ni * 8 + b_row) * KSTRIDE + k16 * 16 + b_koff) * 2);
#pragma unroll
                for (int ni = 0; ni < 4; ni++)
#pragma unroll
                    for (int mi = 0; mi < 4; mi++)
                        mma_bf16(acc[mi][ni], a[mi], bl[ni][0], bl[ni][1]);
            }
#pragma unroll
            for (int mi = 0; mi < 4; mi++)
                ldsm_x4(a[mi][0], a[mi][1], a[mi][2], a[mi][3],
                        st + G_TILE_B + ((wm * 64 + mi * 16 + a_row) * KSTRIDE + k16 * 16 + a_koff) * 2);
#pragma unroll
            for (int ni = 0; ni < 4; ni++)
#pragma unroll
                for (int mi = 0; mi < 4; mi++)
                    mma_bf16(acc[mi][ni], a[mi], bh[ni][0], bh[ni][1]);
        }
        __syncthreads();
        if (c + 2 < 32) load_chunk(c + 2, buf);
    }

    const int gid = lane >> 2, tig = lane & 3;
#pragma unroll
    for (int mi = 0; mi < 4; mi++) {
#pragma unroll
        for (int half = 0; half < 2; half++) {
            const int m = m0 + wm * 64 + mi * 16 + gid + half * 8;
            const int bb = m >> 11, s = m & 2047;
#pragma unroll
            for (int ni = 0; ni < 4; ni++) {
                const int n = n0 + wn * 32 + ni * 8 + tig * 2;
                float c0 = acc[mi][ni][half * 2 + 0] + bias[n];
                float c1 = acc[mi][ni][half * 2 + 1] + bias[n + 1];
                if (mode == 0) {
                    const int h = n >> 6, d = n & 63;
                    size_t o = (((size_t)bb * N_HEADS + h) * S_LEN + s) * DK + d;
                    if (z == 0) {
                        *(__half2*)&g_Qf[o] = __floats2half2_rn(c0 * 0.125f, c1 * 0.125f);
                    } else if (z == 1) {
                        c0 += kpe[((size_t)h * DK + d) * S_LEN + s];
                        c1 += kpe[((size_t)h * DK + d + 1) * S_LEN + s];
                        *(__half2*)&g_Kf[o] = __floats2half2_rn(c0, c1);
                    } else {
                        *(float2*)&g_Vh[o] = make_float2(c0, c1);
                    }
                } else {
                    *(float2*)&out_final[(size_t)m * D_MODEL + n] = make_float2(c0, c1);
                }
            }
        }
    }
}

// ======================= fp16 register-resident flash attention, 2-way split-K =======================
#define AT_KSTR 72
#define FQ_OFF  0
#define FK_OFF  18432
#define FV_OFF  (FK_OFF + 2 * 9216)
#define ATTN_SMEM4 (FV_OFF + 2 * 9216)   // 55296 B
#define SPLIT_TILES 16

__global__ __launch_bounds__(256)
void attn_mma_kernel()
{
    extern __shared__ char smc[];
    const uint32_t base = smem_u32(smc);

    const int tid = threadIdx.x;
    const int wid = tid >> 5, lane = tid & 31;
    const int q0 = blockIdx.x * 128;
    const int h = blockIdx.y;
    const int bz = blockIdx.z >> 1, sp = blockIdx.z & 1;
    const int bh = bz * N_HEADS + h;
    const int T0 = sp * SPLIT_TILES;

    const int a_row = (lane & 15), a_koff = (lane >> 4) * 8;
    const int b_row4 = (lane & 7) + ((lane >> 4) << 3);
    const int b_koff4 = ((lane >> 3) & 1) * 8;
    const int gid = lane >> 2, tig = lane & 3;

    // ---- load Q fragments (fp16, single set) ----
    uint32_t qf[4][4];
    {
#pragma unroll
        for (int it = 0; it < 4; it++) {
            int idx = tid + it * 256;
            int row = idx >> 3, cp = idx & 7;
            cp16(base + FQ_OFF + (row * AT_KSTR + cp * 8) * 2,
                 g_Qf + ((size_t)bh * S_LEN + q0 + row) * DK + cp * 8);
        }
        asm volatile("cp.async.commit_group;" ::: "memory");
        asm volatile("cp.async.wait_group 0;" ::: "memory");
        __syncthreads();
#pragma unroll
        for (int k16 = 0; k16 < 4; k16++)
            ldsm_x4(qf[k16][0], qf[k16][1], qf[k16][2], qf[k16][3],
                    base + FQ_OFF + ((wid * 16 + a_row) * AT_KSTR + k16 * 16 + a_koff) * 2);
        __syncthreads();
    }

    auto load_kv = [&](int T, int bufx) {
        const int t0 = T * 64;
#pragma unroll
        for (int hf = 0; hf < 2; hf++) {
            int rem = tid + hf * 256;
            int row = rem >> 3, cp = rem & 7;
            cp16(base + FK_OFF + bufx * 9216 + (row * AT_KSTR + cp * 8) * 2,
                 g_Kf + ((size_t)bh * S_LEN + t0 + row) * DK + cp * 8);
            cp16(base + FV_OFF + bufx * 9216 + (row * AT_KSTR + cp * 8) * 2,
                 g_Vtf + ((size_t)bh * DK + row) * S_LEN + t0 + cp * 8);
        }
        asm volatile("cp.async.commit_group;" ::: "memory");
    };

    float oacc[8][4];
#pragma unroll
    for (int ni = 0; ni < 8; ni++)
#pragma unroll
        for (int c = 0; c < 4; c++) oacc[ni][c] = 0.f;
    float m0 = -1e30f, m1 = -1e30f, l0 = 0.f, l1 = 0.f;

    load_kv(T0, 0);

#pragma unroll 1
    for (int Ti = 0; Ti < SPLIT_TILES; Ti++) {
        const int buf = Ti & 1;
        asm volatile("cp.async.wait_group 0;" ::: "memory");
        __syncthreads();
        if (Ti + 1 < SPLIT_TILES) load_kv(T0 + Ti + 1, buf ^ 1);

        const uint32_t kb = base + FK_OFF + buf * 9216;
        const uint32_t vb = base + FV_OFF + buf * 9216;

        // ---- QK^T (single fp16 pass) ----
        float sacc[8][4];
#pragma unroll
        for (int ni = 0; ni < 8; ni++)
#pragma unroll
            for (int c = 0; c < 4; c++) sacc[ni][c] = 0.f;

#pragma unroll
        for (int kd = 0; kd < 4; kd++) {
            uint32_t kf[4][4];
#pragma unroll
            for (int np = 0; np < 4; np++)
                ldsm_x4(kf[np][0], kf[np][1], kf[np][2], kf[np][3],
                        kb + ((np * 16 + b_row4) * AT_KSTR + kd * 16 + b_koff4) * 2);
#pragma unroll
            for (int np = 0; np < 4; np++) {
                mma_f16(sacc[2 * np],     qf[kd], kf[np][0], kf[np][1]);
                mma_f16(sacc[2 * np + 1], qf[kd], kf[np][2], kf[np][3]);
            }
        }

        // ---- register softmax ----
        float mx0 = -1e30f, mx1 = -1e30f;
#pragma unroll
        for (int ni = 0; ni < 8; ni++) {
            mx0 = fmaxf(mx0, fmaxf(sacc[ni][0], sacc[ni][1]));
            mx1 = fmaxf(mx1, fmaxf(sacc[ni][2], sacc[ni][3]));
        }
        mx0 = fmaxf(mx0, __shfl_xor_sync(0xffffffffu, mx0, 1));
        mx0 = fmaxf(mx0, __shfl_xor_sync(0xffffffffu, mx0, 2));
        mx1 = fmaxf(mx1, __shfl_xor_sync(0xffffffffu, mx1, 1));
        mx1 = fmaxf(mx1, __shfl_xor_sync(0xffffffffu, mx1, 2));

        const float mn0 = fmaxf(m0, mx0), mn1 = fmaxf(m1, mx1);
        const float cr0 = __expf(m0 - mn0), cr1 = __expf(m1 - mn1);
        m0 = mn0; m1 = mn1;

        float s0 = 0.f, s1 = 0.f;
#pragma unroll
        for (int ni = 0; ni < 8; ni++) {
            sacc[ni][0] = __expf(sacc[ni][0] - mn0);
            sacc[ni][1] = __expf(sacc[ni][1] - mn0);
            sacc[ni][2] = __expf(sacc[ni][2] - mn1);
            sacc[ni][3] = __expf(sacc[ni][3] - mn1);
            s0 += sacc[ni][0] + sacc[ni][1];
            s1 += sacc[ni][2] + sacc[ni][3];
        }
        s0 += __shfl_xor_sync(0xffffffffu, s0, 1);
        s0 += __shfl_xor_sync(0xffffffffu, s0, 2);
        s1 += __shfl_xor_sync(0xffffffffu, s1, 1);
        s1 += __shfl_xor_sync(0xffffffffu, s1, 2);
        l0 = l0 * cr0 + s0;
        l1 = l1 * cr1 + s1;

#pragma unroll
        for (int ni = 0; ni < 8; ni++) {
            oacc[ni][0] *= cr0; oacc[ni][1] *= cr0;
            oacc[ni][2] *= cr1; oacc[ni][3] *= cr1;
        }

        // ---- P fragments (fp16, no split) ----
        uint32_t pf[4][4];
#pragma unroll
        for (int kt = 0; kt < 4; kt++) {
            const float* e0 = sacc[2 * kt];
            const float* e1 = sacc[2 * kt + 1];
            pf[kt][0] = pack_h2(e0[0], e0[1]);
            pf[kt][1] = pack_h2(e0[2], e0[3]);
            pf[kt][2] = pack_h2(e1[0], e1[1]);
            pf[kt][3] = pack_h2(e1[2], e1[3]);
        }

        // ---- PV (single fp16 pass) ----
#pragma unroll
        for (int kt = 0; kt < 4; kt++) {
            uint32_t vf[4][4];
#pragma unroll
            for (int np = 0; np < 4; np++)
                ldsm_x4(vf[np][0], vf[np][1], vf[np][2], vf[np][3],
                        vb + ((np * 16 + b_row4) * AT_KSTR + kt * 16 + b_koff4) * 2);
#pragma unroll
            for (int np = 0; np < 4; np++) {
                mma_f16(oacc[2 * np],     pf[kt], vf[np][0], vf[np][1]);
                mma_f16(oacc[2 * np + 1], pf[kt], vf[np][2], vf[np][3]);
            }
        }
    }

    // ---- epilogue: raw partials + (m, l) ----
#pragma unroll
    for (int hf = 0; hf < 2; hf++) {
        const int s = q0 + wid * 16 + gid + hf * 8;
        const size_t row = (size_t)bh * S_LEN + s;
#pragma unroll
        for (int ni = 0; ni < 8; ni++) {
            const int d = ni * 8 + tig * 2;
            *(float2*)&g_Opart[sp][row * DK + d] =
                make_float2(oacc[ni][hf * 2 + 0], oacc[ni][hf * 2 + 1]);
        }
        if (tig == 0)
            g_MLpart[sp][row] = make_float2(hf ? m1 : m0, hf ? l1 : l0);
    }
}

// combine the two split-K halves -> bf16 hi/lo attention output
__global__ __launch_bounds__(256) void attn_combine_kernel()
{
    size_t idx = ((size_t)blockIdx.x * 256 + threadIdx.x) * 4;
    size_t r = idx >> 6;
    int d = (int)(idx & 63);
    float2 ml0 = g_MLpart[0][r], ml1 = g_MLpart[1][r];
    float m = fmaxf(ml0.x, ml1.x);
    float c0 = __expf(ml0.x - m), c1 = __expf(ml1.x - m);
    float inv = 1.f / (c0 * ml0.y + c1 * ml1.y);
    float4 o0 = *(float4*)&g_Opart[0][idx];
    float4 o1 = *(float4*)&g_Opart[1][idx];
    float v0 = (c0 * o0.x + c1 * o1.x) * inv;
    float v1 = (c0 * o0.y + c1 * o1.y) * inv;
    float v2 = (c0 * o0.z + c1 * o1.z) * inv;
    float v3 = (c0 * o0.w + c1 * o1.w) * inv;

    int bz = (int)(r / (N_HEADS * S_LEN));
    int h  = (int)((r / S_LEN) % N_HEADS);
    int s  = (int)(r % S_LEN);
    size_t o = ((size_t)bz * S_LEN + s) * D_MODEL + h * DK + d;

    __nv_bfloat16 h0,l0,h1,l1,h2,l2,h3,l3;
    split1(v0,h0,l0); split1(v1,h1,l1); split1(v2,h2,l2); split1(v3,h3,l3);
    *(__nv_bfloat162*)&g_Oh[o]     = __nv_bfloat162(h0, h1);
    *(__nv_bfloat162*)&g_Oh[o + 2] = __nv_bfloat162(h2, h3);
    *(__nv_bfloat162*)&g_Ol[o]     = __nv_bfloat162(l0, l1);
    *(__nv_bfloat162*)&g_Ol[o + 2] = __nv_bfloat162(l2, l3);
}

// =====================================================================
extern "C" void kernel_launch(void* const* d_in, const int* in_sizes, int n_in,
                              void* d_out, int out_size)
{
    const float* q   = (const float*)d_in[0];
    const float* k   = (const float*)d_in[1];
    const float* v   = (const float*)d_in[2];
    const float* kpe = (const float*)d_in[3];
    const float* Wq  = (const float*)d_in[4];
    const float* bq  = (const float*)d_in[5];
    const float* Wk  = (const float*)d_in[6];
    const float* bk  = (const float*)d_in[7];
    const float* Wv  = (const float*)d_in[8];
    const float* bv  = (const float*)d_in[9];
    const float* Wo  = (const float*)d_in[10];
    const float* bo  = (const float*)d_in[11];
    float* out = (float*)d_out;

    cudaFuncSetAttribute(attn_mma_kernel, cudaFuncAttributeMaxDynamicSharedMemorySize,
                         ATTN_SMEM4);
    cudaFuncSetAttribute(gemm_bf16_kernel, cudaFuncAttributeMaxDynamicSharedMemorySize,
                         GEMM_SMEM);

    // prep: split inputs + weights to bf16 hi/lo
    dim3 gs(M_ROWS * D_MODEL / 1024, 3);
    split_qkv_kernel<<<gs, 256>>>(q, k, v);
    dim3 gw(32, 32, 4);
    splitW_kernel<<<gw, dim3(32, 8)>>>(Wq, Wk, Wv, Wo);

    // Q/K/V projections
    dim3 gp(D_MODEL / BN, M_ROWS / BM, 3);
    gemm_bf16_kernel<<<gp, 256, GEMM_SMEM>>>(0, kpe, bq, bk, bv, bo, out);

    // V transpose (fp16)
    dim3 gv(DK / 32, S_LEN / 32, B_SIZE * N_HEADS);
    vtrans_kernel<<<gv, dim3(32, 8)>>>();

    // attention (fp16 tensor cores, register-resident P, 2-way split-K)
    dim3 ga(S_LEN / 128, N_HEADS, B_SIZE * 2);
    attn_mma_kernel<<<ga, 256, ATTN_SMEM4>>>();
    attn_combine_kernel<<<BHS * DK / 1024, 256>>>();

    // output projection
    dim3 go(D_MODEL / BN, M_ROWS / BM, 1);
    gemm_bf16_kernel<<<go, 256, GEMM_SMEM>>>(1, kpe, bq, bk, bv, bo, out);
}

// round 11
// speedup vs baseline: 2.3300x; 1.1297x over previous
#include <cuda_runtime.h>
#include <cuda_bf16.h>
#include <cuda_fp16.h>
#include <cstdint>

#define D_MODEL 1024
#define N_HEADS 16
#define DK      64
#define B_SIZE  2
#define S_LEN   2048
#define M_ROWS  (B_SIZE * S_LEN)   // 4096
#define BHS     (B_SIZE * N_HEADS * S_LEN)

// ---------------- scratch ----------------
__device__ __nv_bfloat16 g_Ah[3][(size_t)M_ROWS * D_MODEL];
__device__ __nv_bfloat16 g_Al[3][(size_t)M_ROWS * D_MODEL];
__device__ __nv_bfloat16 g_Wth[3][(size_t)D_MODEL * D_MODEL];  // W^T hi [n][k] (q,k,v)
__device__ __nv_bfloat16 g_Wtl[3][(size_t)D_MODEL * D_MODEL];  // W^T lo [n][k]
__device__ __half        g_Wtf[(size_t)D_MODEL * D_MODEL];     // Wo^T fp16 [n][k]

// attention operands (fp16)
__device__ __half g_Qf[(size_t)M_ROWS * D_MODEL];              // [B,H,S,DK], scaled 1/8
__device__ __half g_Kf[(size_t)M_ROWS * D_MODEL];              // [B,H,S,DK] (K + kpe)
__device__ __half g_Vf[(size_t)M_ROWS * D_MODEL];              // [B,H,S,DK]
__device__ __half g_Of[(size_t)M_ROWS * D_MODEL];              // attn out [B,S,D] fp16

// split-K attention partials
__device__ float  g_Opart[2][(size_t)BHS * DK];
__device__ float2 g_MLpart[2][BHS];

// ======================= helpers =======================
__device__ __forceinline__ uint32_t smem_u32(const void* p) {
    uint32_t a;
    asm("{ .reg .u64 t; cvta.to.shared.u64 t, %1; cvt.u32.u64 %0, t; }" : "=r"(a) : "l"(p));
    return a;
}
__device__ __forceinline__ void cp16(uint32_t dst, const void* src) {
    asm volatile("cp.async.cg.shared.global [%0], [%1], 16;" :: "r"(dst), "l"(src));
}
__device__ __forceinline__ void ldsm_x4(uint32_t& r0, uint32_t& r1, uint32_t& r2, uint32_t& r3, uint32_t addr) {
    asm volatile("ldmatrix.sync.aligned.m8n8.x4.shared.b16 {%0,%1,%2,%3}, [%4];"
        : "=r"(r0), "=r"(r1), "=r"(r2), "=r"(r3) : "r"(addr));
}
__device__ __forceinline__ void ldsm_x4_t(uint32_t& r0, uint32_t& r1, uint32_t& r2, uint32_t& r3, uint32_t addr) {
    asm volatile("ldmatrix.sync.aligned.m8n8.x4.trans.shared.b16 {%0,%1,%2,%3}, [%4];"
        : "=r"(r0), "=r"(r1), "=r"(r2), "=r"(r3) : "r"(addr));
}
__device__ __forceinline__ void ldsm_x2(uint32_t& r0, uint32_t& r1, uint32_t addr) {
    asm volatile("ldmatrix.sync.aligned.m8n8.x2.shared.b16 {%0,%1}, [%2];"
        : "=r"(r0), "=r"(r1) : "r"(addr));
}
__device__ __forceinline__ void mma_bf16(float* c, const uint32_t* a, uint32_t b0, uint32_t b1) {
    asm volatile("mma.sync.aligned.m16n8k16.row.col.f32.bf16.bf16.f32 "
        "{%0,%1,%2,%3}, {%4,%5,%6,%7}, {%8,%9}, {%0,%1,%2,%3};"
        : "+f"(c[0]), "+f"(c[1]), "+f"(c[2]), "+f"(c[3])
        : "r"(a[0]), "r"(a[1]), "r"(a[2]), "r"(a[3]), "r"(b0), "r"(b1));
}
__device__ __forceinline__ void mma_f16(float* c, const uint32_t* a, uint32_t b0, uint32_t b1) {
    asm volatile("mma.sync.aligned.m16n8k16.row.col.f32.f16.f16.f32 "
        "{%0,%1,%2,%3}, {%4,%5,%6,%7}, {%8,%9}, {%0,%1,%2,%3};"
        : "+f"(c[0]), "+f"(c[1]), "+f"(c[2]), "+f"(c[3])
        : "r"(a[0]), "r"(a[1]), "r"(a[2]), "r"(a[3]), "r"(b0), "r"(b1));
}
__device__ __forceinline__ void split1(float x, __nv_bfloat16& h, __nv_bfloat16& l) {
    h = __float2bfloat16_rn(x);
    l = __float2bfloat16_rn(x - __bfloat162float(h));
}
__device__ __forceinline__ uint32_t pack_h2(float a, float b) {
    __half2 t = __floats2half2_rn(a, b);
    return *(uint32_t*)&t;
}

// ======================= prep kernels =======================
__global__ __launch_bounds__(256) void split_qkv_kernel(
    const float* __restrict__ q, const float* __restrict__ k, const float* __restrict__ v)
{
    int z = blockIdx.y;
    const float* src = (z == 0) ? q : (z == 1) ? k : v;
    __nv_bfloat16* hi = g_Ah[z];
    __nv_bfloat16* lo = g_Al[z];
    size_t i = ((size_t)blockIdx.x * 256 + threadIdx.x) * 4;
    float4 a = *(const float4*)(src + i);
    __nv_bfloat16 h0,h1,h2,h3,l0,l1,l2,l3;
    split1(a.x,h0,l0); split1(a.y,h1,l1); split1(a.z,h2,l2); split1(a.w,h3,l3);
    *(__nv_bfloat162*)(hi+i)   = __nv_bfloat162(h0,h1);
    *(__nv_bfloat162*)(hi+i+2) = __nv_bfloat162(h2,h3);
    *(__nv_bfloat162*)(lo+i)   = __nv_bfloat162(l0,l1);
    *(__nv_bfloat162*)(lo+i+2) = __nv_bfloat162(l2,l3);
}

__global__ void splitW_kernel(
    const float* __restrict__ Wq, const float* __restrict__ Wk,
    const float* __restrict__ Wv, const float* __restrict__ Wo)
{
    __shared__ float sm[32][33];
    int z = blockIdx.z;
    const float* W = (z == 0) ? Wq : (z == 1) ? Wk : (z == 2) ? Wv : Wo;
    int n0 = blockIdx.x * 32, k0 = blockIdx.y * 32;
    int tx = threadIdx.x, ty = threadIdx.y;
#pragma unroll
    for (int i = 0; i < 4; i++)
        sm[ty + 8 * i][tx] = W[(size_t)(k0 + ty + 8 * i) * D_MODEL + n0 + tx];
    __syncthreads();
#pragma unroll
    for (int i = 0; i < 4; i++) {
        int c = ty + 8 * i;
        float vv = sm[tx][c];
        size_t o = (size_t)(n0 + c) * D_MODEL + k0 + tx;
        if (z < 3) {
            __nv_bfloat16 h, l;
            split1(vv, h, l);
            g_Wth[z][o] = h;
            g_Wtl[z][o] = l;
        } else {
            g_Wtf[o] = __float2half_rn(vv);
        }
    }
}

// ======================= fused-pass mma.sync bf16 split GEMM (Q/K/V proj) =======================
#define BM 128
#define BN 128
#define KSTRIDE 40
#define G_TILE_B (128 * KSTRIDE * 2)
#define G_STAGE_B (4 * G_TILE_B)
#define GEMM_SMEM (2 * G_STAGE_B)

__global__ __launch_bounds__(256)
void gemm_bf16_kernel(const float* __restrict__ kpe,
                      const float* __restrict__ bq, const float* __restrict__ bk,
                      const float* __restrict__ bv)
{
    extern __shared__ char sgem[];
    const uint32_t sbase = smem_u32(sgem);

    const int z = blockIdx.z;
    const __nv_bfloat16* Ahp = g_Ah[z];
    const __nv_bfloat16* Alp = g_Al[z];
    const __nv_bfloat16* Whp = g_Wth[z];
    const __nv_bfloat16* Wlp = g_Wtl[z];
    const float* bias = (z == 0) ? bq : (z == 1) ? bk : bv;

    const int m0 = blockIdx.y * BM;
    const int n0 = blockIdx.x * BN;
    const int tid = threadIdx.x;
    const int wid = tid >> 5, lane = tid & 31;
    const int wm = wid & 1, wn = wid >> 1;

    const int lrow = tid >> 1, lcp = tid & 1;

    auto load_chunk = [&](int kc, int buf) {
        const size_t ga = (size_t)(m0 + lrow) * D_MODEL + kc * 32 + lcp * 16;
        const size_t gb = (size_t)(n0 + lrow) * D_MODEL + kc * 32 + lcp * 16;
        const uint32_t so = sbase + buf * G_STAGE_B + (lrow * KSTRIDE + lcp * 16) * 2;
        cp16(so,                     Ahp + ga); cp16(so + 16,                Ahp + ga + 8);
        cp16(so + G_TILE_B,          Alp + ga); cp16(so + G_TILE_B + 16,     Alp + ga + 8);
        cp16(so + 2 * G_TILE_B,      Whp + gb); cp16(so + 2 * G_TILE_B + 16, Whp + gb + 8);
        cp16(so + 3 * G_TILE_B,      Wlp + gb); cp16(so + 3 * G_TILE_B + 16, Wlp + gb + 8);
        asm volatile("cp.async.commit_group;" ::: "memory");
    };

    float acc[4][4][4];
#pragma unroll
    for (int i = 0; i < 4; i++)
#pragma unroll
        for (int j = 0; j < 4; j++)
#pragma unroll
            for (int c = 0; c < 4; c++) acc[i][j][c] = 0.f;

    load_chunk(0, 0);
    load_chunk(1, 1);

    const int a_row = (lane & 15), a_koff = (lane >> 4) * 8;
    const int b_row = (lane & 7),  b_koff = ((lane >> 3) & 1) * 8;

    for (int c = 0; c < 32; c++) {
        const int buf = c & 1;
        if (c < 31) asm volatile("cp.async.wait_group 1;" ::: "memory");
        else        asm volatile("cp.async.wait_group 0;" ::: "memory");
        __syncthreads();

        const uint32_t st = sbase + buf * G_STAGE_B;
#pragma unroll
        for (int k16 = 0; k16 < 2; k16++) {
            uint32_t a[4][4], bh[4][2];
#pragma unroll
            for (int mi = 0; mi < 4; mi++)
                ldsm_x4(a[mi][0], a[mi][1], a[mi][2], a[mi][3],
                        st + ((wm * 64 + mi * 16 + a_row) * KSTRIDE + k16 * 16 + a_koff) * 2);
#pragma unroll
            for (int ni = 0; ni < 4; ni++)
                ldsm_x2(bh[ni][0], bh[ni][1],
                        st + 2 * G_TILE_B + ((wn * 32 + ni * 8 + b_row) * KSTRIDE + k16 * 16 + b_koff) * 2);
#pragma unroll
            for (int ni = 0; ni < 4; ni++)
#pragma unroll
                for (int mi = 0; mi < 4; mi++)
                    mma_bf16(acc[mi][ni], a[mi], bh[ni][0], bh[ni][1]);
            {
                uint32_t bl[4][2];
#pragma unroll
                for (int ni = 0; ni < 4; ni++)
                    ldsm_x2(bl[ni][0], bl[ni][1],
                            st + 3 * G_TILE_B + ((wn * 32 + ni * 8 + b_row) * KSTRIDE + k16 * 16 + b_koff) * 2);
#pragma unroll
                for (int ni = 0; ni < 4; ni++)
#pragma unroll
                    for (int mi = 0; mi < 4; mi++)
                        mma_bf16(acc[mi][ni], a[mi], bl[ni][0], bl[ni][1]);
            }
#pragma unroll
            for (int mi = 0; mi < 4; mi++)
                ldsm_x4(a[mi][0], a[mi][1], a[mi][2], a[mi][3],
                        st + G_TILE_B + ((wm * 64 + mi * 16 + a_row) * KSTRIDE + k16 * 16 + a_koff) * 2);
#pragma unroll
            for (int ni = 0; ni < 4; ni++)
#pragma unroll
                for (int mi = 0; mi < 4; mi++)
                    mma_bf16(acc[mi][ni], a[mi], bh[ni][0], bh[ni][1]);
        }
        __syncthreads();
        if (c + 2 < 32) load_chunk(c + 2, buf);
    }

    const int gid = lane >> 2, tig = lane & 3;
#pragma unroll
    for (int mi = 0; mi < 4; mi++) {
#pragma unroll
        for (int half = 0; half < 2; half++) {
            const int m = m0 + wm * 64 + mi * 16 + gid + half * 8;
            const int bb = m >> 11, s = m & 2047;
#pragma unroll
            for (int ni = 0; ni < 4; ni++) {
                const int n = n0 + wn * 32 + ni * 8 + tig * 2;
                float c0 = acc[mi][ni][half * 2 + 0] + bias[n];
                float c1 = acc[mi][ni][half * 2 + 1] + bias[n + 1];
                const int h = n >> 6, d = n & 63;
                size_t o = (((size_t)bb * N_HEADS + h) * S_LEN + s) * DK + d;
                if (z == 0) {
                    *(__half2*)&g_Qf[o] = __floats2half2_rn(c0 * 0.125f, c1 * 0.125f);
                } else if (z == 1) {
                    c0 += kpe[((size_t)h * DK + d) * S_LEN + s];
                    c1 += kpe[((size_t)h * DK + d + 1) * S_LEN + s];
                    *(__half2*)&g_Kf[o] = __floats2half2_rn(c0, c1);
                } else {
                    *(__half2*)&g_Vf[o] = __floats2half2_rn(c0, c1);
                }
            }
        }
    }
}

// ======================= fp16 single-pass output projection =======================
#define OP_STAGE_B (2 * 128 * KSTRIDE * 2)   // A + B tile per stage = 20480
__global__ __launch_bounds__(256)
void outproj_f16_kernel(const float* __restrict__ bo, float* __restrict__ out_final)
{
    __shared__ __half sop[2][2 * 128 * KSTRIDE];

    const int m0 = blockIdx.y * BM;
    const int n0 = blockIdx.x * BN;
    const int tid = threadIdx.x;
    const int wid = tid >> 5, lane = tid & 31;
    const int wm = wid & 1, wn = wid >> 1;
    const uint32_t sbase = smem_u32(sop[0]);
    const int lrow = tid >> 1, lcp = tid & 1;

    auto load_chunk = [&](int kc, int buf) {
        const size_t ga = (size_t)(m0 + lrow) * D_MODEL + kc * 32 + lcp * 16;
        const size_t gb = (size_t)(n0 + lrow) * D_MODEL + kc * 32 + lcp * 16;
        const uint32_t so = sbase + buf * OP_STAGE_B + (lrow * KSTRIDE + lcp * 16) * 2;
        cp16(so, g_Of + ga);                      cp16(so + 16, g_Of + ga + 8);
        cp16(so + G_TILE_B, g_Wtf + gb);          cp16(so + G_TILE_B + 16, g_Wtf + gb + 8);
        asm volatile("cp.async.commit_group;" ::: "memory");
    };

    float acc[4][4][4];
#pragma unroll
    for (int i = 0; i < 4; i++)
#pragma unroll
        for (int j = 0; j < 4; j++)
#pragma unroll
            for (int c = 0; c < 4; c++) acc[i][j][c] = 0.f;

    load_chunk(0, 0);
    load_chunk(1, 1);

    const int a_row = (lane & 15), a_koff = (lane >> 4) * 8;
    const int b_row = (lane & 7),  b_koff = ((lane >> 3) & 1) * 8;

    for (int c = 0; c < 32; c++) {
        const int buf = c & 1;
        if (c < 31) asm volatile("cp.async.wait_group 1;" ::: "memory");
        else        asm volatile("cp.async.wait_group 0;" ::: "memory");
        __syncthreads();

        const uint32_t st = sbase + buf * OP_STAGE_B;
#pragma unroll
        for (int k16 = 0; k16 < 2; k16++) {
            uint32_t a[4][4], bf[4][2];
#pragma unroll
            for (int mi = 0; mi < 4; mi++)
                ldsm_x4(a[mi][0], a[mi][1], a[mi][2], a[mi][3],
                        st + ((wm * 64 + mi * 16 + a_row) * KSTRIDE + k16 * 16 + a_koff) * 2);
#pragma unroll
            for (int ni = 0; ni < 4; ni++)
                ldsm_x2(bf[ni][0], bf[ni][1],
                        st + G_TILE_B + ((wn * 32 + ni * 8 + b_row) * KSTRIDE + k16 * 16 + b_koff) * 2);
#pragma unroll
            for (int ni = 0; ni < 4; ni++)
#pragma unroll
                for (int mi = 0; mi < 4; mi++)
                    mma_f16(acc[mi][ni], a[mi], bf[ni][0], bf[ni][1]);
        }
        __syncthreads();
        if (c + 2 < 32) load_chunk(c + 2, buf);
    }

    const int gid = lane >> 2, tig = lane & 3;
#pragma unroll
    for (int mi = 0; mi < 4; mi++) {
#pragma unroll
        for (int half = 0; half < 2; half++) {
            const int m = m0 + wm * 64 + mi * 16 + gid + half * 8;
#pragma unroll
            for (int ni = 0; ni < 4; ni++) {
                const int n = n0 + wn * 32 + ni * 8 + tig * 2;
                *(float2*)&out_final[(size_t)m * D_MODEL + n] =
                    make_float2(acc[mi][ni][half * 2 + 0] + bo[n],
                                acc[mi][ni][half * 2 + 1] + bo[n + 1]);
            }
        }
    }
}

// ======================= fp16 register-resident flash attention, 2-way split-K =======================
#define AT_KSTR 72
#define FQ_OFF  0
#define FK_OFF  18432
#define FV_OFF  (FK_OFF + 2 * 9216)
#define ATTN_SMEM4 (FV_OFF + 2 * 9216)   // 55296 B
#define SPLIT_TILES 16

__global__ __launch_bounds__(256)
void attn_mma_kernel()
{
    extern __shared__ char smc[];
    const uint32_t base = smem_u32(smc);

    const int tid = threadIdx.x;
    const int wid = tid >> 5, lane = tid & 31;
    const int q0 = blockIdx.x * 128;
    const int h = blockIdx.y;
    const int bz = blockIdx.z >> 1, sp = blockIdx.z & 1;
    const int bh = bz * N_HEADS + h;
    const int T0 = sp * SPLIT_TILES;

    const int a_row = (lane & 15), a_koff = (lane >> 4) * 8;
    const int b_row4 = (lane & 7) + ((lane >> 4) << 3);
    const int b_koff4 = ((lane >> 3) & 1) * 8;
    // trans-load mapping (V): group g = lane>>3: rows k, col-8-block g>>1
    const int t_row = (lane & 7) + (((lane >> 3) & 1) << 3);
    const int t_col8 = (lane >> 4) * 8;
    const int gid = lane >> 2, tig = lane & 3;

    // ---- load Q fragments ----
    uint32_t qf[4][4];
    {
#pragma unroll
        for (int it = 0; it < 4; it++) {
            int idx = tid + it * 256;
            int row = idx >> 3, cp = idx & 7;
            cp16(base + FQ_OFF + (row * AT_KSTR + cp * 8) * 2,
                 g_Qf + ((size_t)bh * S_LEN + q0 + row) * DK + cp * 8);
        }
        asm volatile("cp.async.commit_group;" ::: "memory");
        asm volatile("cp.async.wait_group 0;" ::: "memory");
        __syncthreads();
#pragma unroll
        for (int k16 = 0; k16 < 4; k16++)
            ldsm_x4(qf[k16][0], qf[k16][1], qf[k16][2], qf[k16][3],
                    base + FQ_OFF + ((wid * 16 + a_row) * AT_KSTR + k16 * 16 + a_koff) * 2);
        __syncthreads();
    }

    auto load_kv = [&](int T, int bufx) {
        const int t0 = T * 64;
#pragma unroll
        for (int hf = 0; hf < 2; hf++) {
            int rem = tid + hf * 256;
            int row = rem >> 3, cp = rem & 7;
            cp16(base + FK_OFF + bufx * 9216 + (row * AT_KSTR + cp * 8) * 2,
                 g_Kf + ((size_t)bh * S_LEN + t0 + row) * DK + cp * 8);
            cp16(base + FV_OFF + bufx * 9216 + (row * AT_KSTR + cp * 8) * 2,
                 g_Vf + ((size_t)bh * S_LEN + t0 + row) * DK + cp * 8);
        }
        asm volatile("cp.async.commit_group;" ::: "memory");
    };

    float oacc[8][4];
#pragma unroll
    for (int ni = 0; ni < 8; ni++)
#pragma unroll
        for (int c = 0; c < 4; c++) oacc[ni][c] = 0.f;
    float m0 = -1e30f, m1 = -1e30f, l0 = 0.f, l1 = 0.f;

    load_kv(T0, 0);

#pragma unroll 1
    for (int Ti = 0; Ti < SPLIT_TILES; Ti++) {
        const int buf = Ti & 1;
        asm volatile("cp.async.wait_group 0;" ::: "memory");
        __syncthreads();
        if (Ti + 1 < SPLIT_TILES) load_kv(T0 + Ti + 1, buf ^ 1);

        const uint32_t kb = base + FK_OFF + buf * 9216;
        const uint32_t vb = base + FV_OFF + buf * 9216;

        // ---- QK^T (fp16) ----
        float sacc[8][4];
#pragma unroll
        for (int ni = 0; ni < 8; ni++)
#pragma unroll
            for (int c = 0; c < 4; c++) sacc[ni][c] = 0.f;

#pragma unroll
        for (int kd = 0; kd < 4; kd++) {
            uint32_t kf[4][4];
#pragma unroll
            for (int np = 0; np < 4; np++)
                ldsm_x4(kf[np][0], kf[np][1], kf[np][2], kf[np][3],
                        kb + ((np * 16 + b_row4) * AT_KSTR + kd * 16 + b_koff4) * 2);
#pragma unroll
            for (int np = 0; np < 4; np++) {
                mma_f16(sacc[2 * np],     qf[kd], kf[np][0], kf[np][1]);
                mma_f16(sacc[2 * np + 1], qf[kd], kf[np][2], kf[np][3]);
            }
        }

        // ---- register softmax ----
        float mx0 = -1e30f, mx1 = -1e30f;
#pragma unroll
        for (int ni = 0; ni < 8; ni++) {
            mx0 = fmaxf(mx0, fmaxf(sacc[ni][0], sacc[ni][1]));
            mx1 = fmaxf(mx1, fmaxf(sacc[ni][2], sacc[ni][3]));
        }
        mx0 = fmaxf(mx0, __shfl_xor_sync(0xffffffffu, mx0, 1));
        mx0 = fmaxf(mx0, __shfl_xor_sync(0xffffffffu, mx0, 2));
        mx1 = fmaxf(mx1, __shfl_xor_sync(0xffffffffu, mx1, 1));
        mx1 = fmaxf(mx1, __shfl_xor_sync(0xffffffffu, mx1, 2));

        const float mn0 = fmaxf(m0, mx0), mn1 = fmaxf(m1, mx1);
        const float cr0 = __expf(m0 - mn0), cr1 = __expf(m1 - mn1);
        m0 = mn0; m1 = mn1;

        float s0 = 0.f, s1 = 0.f;
#pragma unroll
        for (int ni = 0; ni < 8; ni++) {
            sacc[ni][0] = __expf(sacc[ni][0] - mn0);
            sacc[ni][1] = __expf(sacc[ni][1] - mn0);
            sacc[ni][2] = __expf(sacc[ni][2] - mn1);
            sacc[ni][3] = __expf(sacc[ni][3] - mn1);
            s0 += sacc[ni][0] + sacc[ni][1];
            s1 += sacc[ni][2] + sacc[ni][3];
        }
        s0 += __shfl_xor_sync(0xffffffffu, s0, 1);
        s0 += __shfl_xor_sync(0xffffffffu, s0, 2);
        s1 += __shfl_xor_sync(0xffffffffu, s1, 1);
        s1 += __shfl_xor_sync(0xffffffffu, s1, 2);
        l0 = l0 * cr0 + s0;
        l1 = l1 * cr1 + s1;

#pragma unroll
        for (int ni = 0; ni < 8; ni++) {
            oacc[ni][0] *= cr0; oacc[ni][1] *= cr0;
            oacc[ni][2] *= cr1; oacc[ni][3] *= cr1;
        }

        // ---- P fragments (fp16) ----
        uint32_t pf[4][4];
#pragma unroll
        for (int kt = 0; kt < 4; kt++) {
            const float* e0 = sacc[2 * kt];
            const float* e1 = sacc[2 * kt + 1];
            pf[kt][0] = pack_h2(e0[0], e0[1]);
            pf[kt][1] = pack_h2(e0[2], e0[3]);
            pf[kt][2] = pack_h2(e1[0], e1[1]);
            pf[kt][3] = pack_h2(e1[2], e1[3]);
        }

        // ---- PV (fp16, V row-major via ldmatrix.trans) ----
#pragma unroll
        for (int kt = 0; kt < 4; kt++) {
            uint32_t vf[4][4];
#pragma unroll
            for (int np = 0; np < 4; np++)
                ldsm_x4_t(vf[np][0], vf[np][1], vf[np][2], vf[np][3],
                          vb + ((kt * 16 + t_row) * AT_KSTR + np * 16 + t_col8) * 2);
#pragma unroll
            for (int np = 0; np < 4; np++) {
                mma_f16(oacc[2 * np],     pf[kt], vf[np][0], vf[np][1]);
                mma_f16(oacc[2 * np + 1], pf[kt], vf[np][2], vf[np][3]);
            }
        }
    }

    // ---- epilogue: raw partials + (m, l) ----
#pragma unroll
    for (int hf = 0; hf < 2; hf++) {
        const int s = q0 + wid * 16 + gid + hf * 8;
        const size_t row = (size_t)bh * S_LEN + s;
#pragma unroll
        for (int ni = 0; ni < 8; ni++) {
            const int d = ni * 8 + tig * 2;
            *(float2*)&g_Opart[sp][row * DK + d] =
                make_float2(oacc[ni][hf * 2 + 0], oacc[ni][hf * 2 + 1]);
        }
        if (tig == 0)
            g_MLpart[sp][row] = make_float2(hf ? m1 : m0, hf ? l1 : l0);
    }
}

// combine the two split-K halves -> fp16 attention output
__global__ __launch_bounds__(256) void attn_combine_kernel()
{
    size_t idx = ((size_t)blockIdx.x * 256 + threadIdx.x) * 4;
    size_t r = idx >> 6;
    int d = (int)(idx & 63);
    float2 ml0 = g_MLpart[0][r], ml1 = g_MLpart[1][r];
    float m = fmaxf(ml0.x, ml1.x);
    float c0 = __expf(ml0.x - m), c1 = __expf(ml1.x - m);
    float inv = 1.f / (c0 * ml0.y + c1 * ml1.y);
    float4 o0 = *(float4*)&g_Opart[0][idx];
    float4 o1 = *(float4*)&g_Opart[1][idx];
    float v0 = (c0 * o0.x + c1 * o1.x) * inv;
    float v1 = (c0 * o0.y + c1 * o1.y) * inv;
    float v2 = (c0 * o0.z + c1 * o1.z) * inv;
    float v3 = (c0 * o0.w + c1 * o1.w) * inv;

    int bz = (int)(r / (N_HEADS * S_LEN));
    int h  = (int)((r / S_LEN) % N_HEADS);
    int s  = (int)(r % S_LEN);
    size_t o = ((size_t)bz * S_LEN + s) * D_MODEL + h * DK + d;

    *(__half2*)&g_Of[o]     = __floats2half2_rn(v0, v1);
    *(__half2*)&g_Of[o + 2] = __floats2half2_rn(v2, v3);
}

// =====================================================================
extern "C" void kernel_launch(void* const* d_in, const int* in_sizes, int n_in,
                              void* d_out, int out_size)
{
    const float* q   = (const float*)d_in[0];
    const float* k   = (const float*)d_in[1];
    const float* v   = (const float*)d_in[2];
    const float* kpe = (const float*)d_in[3];
    const float* Wq  = (const float*)d_in[4];
    const float* bq  = (const float*)d_in[5];
    const float* Wk  = (const float*)d_in[6];
    const float* bk  = (const float*)d_in[7];
    const float* Wv  = (const float*)d_in[8];
    const float* bv  = (const float*)d_in[9];
    const float* Wo  = (const float*)d_in[10];
    const float* bo  = (const float*)d_in[11];
    float* out = (float*)d_out;

    cudaFuncSetAttribute(attn_mma_kernel, cudaFuncAttributeMaxDynamicSharedMemorySize,
                         ATTN_SMEM4);
    cudaFuncSetAttribute(gemm_bf16_kernel, cudaFuncAttributeMaxDynamicSharedMemorySize,
                         GEMM_SMEM);

    // prep: split inputs + weights
    dim3 gs(M_ROWS * D_MODEL / 1024, 3);
    split_qkv_kernel<<<gs, 256>>>(q, k, v);
    dim3 gw(32, 32, 4);
    splitW_kernel<<<gw, dim3(32, 8)>>>(Wq, Wk, Wv, Wo);

    // Q/K/V projections (bf16 3-pass, fp16 outputs)
    dim3 gp(D_MODEL / BN, M_ROWS / BM, 3);
    gemm_bf16_kernel<<<gp, 256, GEMM_SMEM>>>(kpe, bq, bk, bv);

    // attention (fp16 tensor cores, register-resident P, 2-way split-K)
    dim3 ga(S_LEN / 128, N_HEADS, B_SIZE * 2);
    attn_mma_kernel<<<ga, 256, ATTN_SMEM4>>>();
    attn_combine_kernel<<<BHS * DK / 1024, 256>>>();

    // output projection (fp16 single pass)
    dim3 go(D_MODEL / BN, M_ROWS / BM, 1);
    outproj_f16_kernel<<<go, 256>>>(bo, out);
}

// round 12
// speedup vs baseline: 2.8611x; 1.2279x over previous
#include <cuda_runtime.h>
#include <cuda_bf16.h>
#include <cuda_fp16.h>
#include <cstdint>

#define D_MODEL 1024
#define N_HEADS 16
#define DK      64
#define B_SIZE  2
#define S_LEN   2048
#define M_ROWS  (B_SIZE * S_LEN)   // 4096
#define BHS     (B_SIZE * N_HEADS * S_LEN)

// ---------------- scratch ----------------
__device__ __half g_Af[3][(size_t)M_ROWS * D_MODEL];           // activations fp16 (q,k,v)
__device__ __half g_Wth[3][(size_t)D_MODEL * D_MODEL];         // W^T hi fp16 [n][k] (q,k,v)
__device__ __half g_Wtl[3][(size_t)D_MODEL * D_MODEL];         // W^T lo fp16 [n][k]
__device__ __half g_Wtf[(size_t)D_MODEL * D_MODEL];            // Wo^T fp16 [n][k]

// attention operands (fp16)
__device__ __half g_Qf[(size_t)M_ROWS * D_MODEL];              // [B,H,S,DK], scaled 1/8
__device__ __half g_Kf[(size_t)M_ROWS * D_MODEL];              // [B,H,S,DK] (K + kpe)
__device__ __half g_Vf[(size_t)M_ROWS * D_MODEL];              // [B,H,S,DK]
__device__ __half g_Of[(size_t)M_ROWS * D_MODEL];              // attn out [B,S,D] fp16

// split-K attention partials
__device__ float  g_Opart[2][(size_t)BHS * DK];
__device__ float2 g_MLpart[2][BHS];

// ======================= helpers =======================
__device__ __forceinline__ uint32_t smem_u32(const void* p) {
    uint32_t a;
    asm("{ .reg .u64 t; cvta.to.shared.u64 t, %1; cvt.u32.u64 %0, t; }" : "=r"(a) : "l"(p));
    return a;
}
__device__ __forceinline__ void cp16(uint32_t dst, const void* src) {
    asm volatile("cp.async.cg.shared.global [%0], [%1], 16;" :: "r"(dst), "l"(src));
}
__device__ __forceinline__ void ldsm_x4(uint32_t& r0, uint32_t& r1, uint32_t& r2, uint32_t& r3, uint32_t addr) {
    asm volatile("ldmatrix.sync.aligned.m8n8.x4.shared.b16 {%0,%1,%2,%3}, [%4];"
        : "=r"(r0), "=r"(r1), "=r"(r2), "=r"(r3) : "r"(addr));
}
__device__ __forceinline__ void ldsm_x4_t(uint32_t& r0, uint32_t& r1, uint32_t& r2, uint32_t& r3, uint32_t addr) {
    asm volatile("ldmatrix.sync.aligned.m8n8.x4.trans.shared.b16 {%0,%1,%2,%3}, [%4];"
        : "=r"(r0), "=r"(r1), "=r"(r2), "=r"(r3) : "r"(addr));
}
__device__ __forceinline__ void ldsm_x2(uint32_t& r0, uint32_t& r1, uint32_t addr) {
    asm volatile("ldmatrix.sync.aligned.m8n8.x2.shared.b16 {%0,%1}, [%2];"
        : "=r"(r0), "=r"(r1) : "r"(addr));
}
__device__ __forceinline__ void mma_f16(float* c, const uint32_t* a, uint32_t b0, uint32_t b1) {
    asm volatile("mma.sync.aligned.m16n8k16.row.col.f32.f16.f16.f32 "
        "{%0,%1,%2,%3}, {%4,%5,%6,%7}, {%8,%9}, {%0,%1,%2,%3};"
        : "+f"(c[0]), "+f"(c[1]), "+f"(c[2]), "+f"(c[3])
        : "r"(a[0]), "r"(a[1]), "r"(a[2]), "r"(a[3]), "r"(b0), "r"(b1));
}
__device__ __forceinline__ uint32_t pack_h2(float a, float b) {
    __half2 t = __floats2half2_rn(a, b);
    return *(uint32_t*)&t;
}

// ======================= prep kernels =======================
// activations -> fp16 single
__global__ __launch_bounds__(256) void cvt_qkv_kernel(
    const float* __restrict__ q, const float* __restrict__ k, const float* __restrict__ v)
{
    int z = blockIdx.y;
    const float* src = (z == 0) ? q : (z == 1) ? k : v;
    __half* dst = g_Af[z];
    size_t i = ((size_t)blockIdx.x * 256 + threadIdx.x) * 4;
    float4 a = *(const float4*)(src + i);
    *(__half2*)(dst + i)     = __floats2half2_rn(a.x, a.y);
    *(__half2*)(dst + i + 2) = __floats2half2_rn(a.z, a.w);
}

// weights: transpose + fp16 hi/lo split (q,k,v); Wo -> fp16 single
__global__ void splitW_kernel(
    const float* __restrict__ Wq, const float* __restrict__ Wk,
    const float* __restrict__ Wv, const float* __restrict__ Wo)
{
    __shared__ float sm[32][33];
    int z = blockIdx.z;
    const float* W = (z == 0) ? Wq : (z == 1) ? Wk : (z == 2) ? Wv : Wo;
    int n0 = blockIdx.x * 32, k0 = blockIdx.y * 32;
    int tx = threadIdx.x, ty = threadIdx.y;
#pragma unroll
    for (int i = 0; i < 4; i++)
        sm[ty + 8 * i][tx] = W[(size_t)(k0 + ty + 8 * i) * D_MODEL + n0 + tx];
    __syncthreads();
#pragma unroll
    for (int i = 0; i < 4; i++) {
        int c = ty + 8 * i;
        float vv = sm[tx][c];
        size_t o = (size_t)(n0 + c) * D_MODEL + k0 + tx;
        if (z < 3) {
            __half h = __float2half_rn(vv);
            g_Wth[z][o] = h;
            g_Wtl[z][o] = __float2half_rn(vv - __half2float(h));
        } else {
            g_Wtf[o] = __float2half_rn(vv);
        }
    }
}

// ======================= 2-pass fp16 GEMM (Q/K/V proj): C = A*(Wh + Wl) =======================
#define BM 128
#define BN 128
#define KSTRIDE 40
#define G_TILE_B (128 * KSTRIDE * 2)       // 10240
#define P_STAGE_B (3 * G_TILE_B)           // A + Wh + Wl = 30720
#define GEMM_SMEM (2 * P_STAGE_B)          // 61440

__global__ __launch_bounds__(256)
void gemm_f16_kernel(const float* __restrict__ kpe,
                     const float* __restrict__ bq, const float* __restrict__ bk,
                     const float* __restrict__ bv)
{
    extern __shared__ char sgem[];
    const uint32_t sbase = smem_u32(sgem);

    const int z = blockIdx.z;
    const __half* Ap  = g_Af[z];
    const __half* Whp = g_Wth[z];
    const __half* Wlp = g_Wtl[z];
    const float* bias = (z == 0) ? bq : (z == 1) ? bk : bv;

    const int m0 = blockIdx.y * BM;
    const int n0 = blockIdx.x * BN;
    const int tid = threadIdx.x;
    const int wid = tid >> 5, lane = tid & 31;
    const int wm = wid & 1, wn = wid >> 1;

    const int lrow = tid >> 1, lcp = tid & 1;

    auto load_chunk = [&](int kc, int buf) {
        const size_t ga = (size_t)(m0 + lrow) * D_MODEL + kc * 32 + lcp * 16;
        const size_t gb = (size_t)(n0 + lrow) * D_MODEL + kc * 32 + lcp * 16;
        const uint32_t so = sbase + buf * P_STAGE_B + (lrow * KSTRIDE + lcp * 16) * 2;
        cp16(so,                Ap + ga);  cp16(so + 16,                Ap + ga + 8);
        cp16(so + G_TILE_B,     Whp + gb); cp16(so + G_TILE_B + 16,     Whp + gb + 8);
        cp16(so + 2 * G_TILE_B, Wlp + gb); cp16(so + 2 * G_TILE_B + 16, Wlp + gb + 8);
        asm volatile("cp.async.commit_group;" ::: "memory");
    };

    float acc[4][4][4];
#pragma unroll
    for (int i = 0; i < 4; i++)
#pragma unroll
        for (int j = 0; j < 4; j++)
#pragma unroll
            for (int c = 0; c < 4; c++) acc[i][j][c] = 0.f;

    load_chunk(0, 0);
    load_chunk(1, 1);

    const int a_row = (lane & 15), a_koff = (lane >> 4) * 8;
    const int b_row = (lane & 7),  b_koff = ((lane >> 3) & 1) * 8;

    for (int c = 0; c < 32; c++) {
        const int buf = c & 1;
        if (c < 31) asm volatile("cp.async.wait_group 1;" ::: "memory");
        else        asm volatile("cp.async.wait_group 0;" ::: "memory");
        __syncthreads();

        const uint32_t st = sbase + buf * P_STAGE_B;
#pragma unroll
        for (int k16 = 0; k16 < 2; k16++) {
            uint32_t a[4][4], bh[4][2];
#pragma unroll
            for (int mi = 0; mi < 4; mi++)
                ldsm_x4(a[mi][0], a[mi][1], a[mi][2], a[mi][3],
                        st + ((wm * 64 + mi * 16 + a_row) * KSTRIDE + k16 * 16 + a_koff) * 2);
#pragma unroll
            for (int ni = 0; ni < 4; ni++)
                ldsm_x2(bh[ni][0], bh[ni][1],
                        st + G_TILE_B + ((wn * 32 + ni * 8 + b_row) * KSTRIDE + k16 * 16 + b_koff) * 2);
#pragma unroll
            for (int ni = 0; ni < 4; ni++)
#pragma unroll
                for (int mi = 0; mi < 4; mi++)
                    mma_f16(acc[mi][ni], a[mi], bh[ni][0], bh[ni][1]);
            {
                uint32_t bl[4][2];
#pragma unroll
                for (int ni = 0; ni < 4; ni++)
                    ldsm_x2(bl[ni][0], bl[ni][1],
                            st + 2 * G_TILE_B + ((wn * 32 + ni * 8 + b_row) * KSTRIDE + k16 * 16 + b_koff) * 2);
#pragma unroll
                for (int ni = 0; ni < 4; ni++)
#pragma unroll
                    for (int mi = 0; mi < 4; mi++)
                        mma_f16(acc[mi][ni], a[mi], bl[ni][0], bl[ni][1]);
            }
        }
        __syncthreads();
        if (c + 2 < 32) load_chunk(c + 2, buf);
    }

    const int gid = lane >> 2, tig = lane & 3;
#pragma unroll
    for (int mi = 0; mi < 4; mi++) {
#pragma unroll
        for (int half = 0; half < 2; half++) {
            const int m = m0 + wm * 64 + mi * 16 + gid + half * 8;
            const int bb = m >> 11, s = m & 2047;
#pragma unroll
            for (int ni = 0; ni < 4; ni++) {
                const int n = n0 + wn * 32 + ni * 8 + tig * 2;
                float c0 = acc[mi][ni][half * 2 + 0] + bias[n];
                float c1 = acc[mi][ni][half * 2 + 1] + bias[n + 1];
                const int h = n >> 6, d = n & 63;
                size_t o = (((size_t)bb * N_HEADS + h) * S_LEN + s) * DK + d;
                if (z == 0) {
                    *(__half2*)&g_Qf[o] = __floats2half2_rn(c0 * 0.125f, c1 * 0.125f);
                } else if (z == 1) {
                    c0 += kpe[((size_t)h * DK + d) * S_LEN + s];
                    c1 += kpe[((size_t)h * DK + d + 1) * S_LEN + s];
                    *(__half2*)&g_Kf[o] = __floats2half2_rn(c0, c1);
                } else {
                    *(__half2*)&g_Vf[o] = __floats2half2_rn(c0, c1);
                }
            }
        }
    }
}

// ======================= fp16 single-pass output projection =======================
#define OP_STAGE_B (2 * 128 * KSTRIDE * 2)   // 20480
__global__ __launch_bounds__(256)
void outproj_f16_kernel(const float* __restrict__ bo, float* __restrict__ out_final)
{
    __shared__ __half sop[2][2 * 128 * KSTRIDE];

    const int m0 = blockIdx.y * BM;
    const int n0 = blockIdx.x * BN;
    const int tid = threadIdx.x;
    const int wid = tid >> 5, lane = tid & 31;
    const int wm = wid & 1, wn = wid >> 1;
    const uint32_t sbase = smem_u32(sop[0]);
    const int lrow = tid >> 1, lcp = tid & 1;

    auto load_chunk = [&](int kc, int buf) {
        const size_t ga = (size_t)(m0 + lrow) * D_MODEL + kc * 32 + lcp * 16;
        const size_t gb = (size_t)(n0 + lrow) * D_MODEL + kc * 32 + lcp * 16;
        const uint32_t so = sbase + buf * OP_STAGE_B + (lrow * KSTRIDE + lcp * 16) * 2;
        cp16(so, g_Of + ga);                      cp16(so + 16, g_Of + ga + 8);
        cp16(so + G_TILE_B, g_Wtf + gb);          cp16(so + G_TILE_B + 16, g_Wtf + gb + 8);
        asm volatile("cp.async.commit_group;" ::: "memory");
    };

    float acc[4][4][4];
#pragma unroll
    for (int i = 0; i < 4; i++)
#pragma unroll
        for (int j = 0; j < 4; j++)
#pragma unroll
            for (int c = 0; c < 4; c++) acc[i][j][c] = 0.f;

    load_chunk(0, 0);
    load_chunk(1, 1);

    const int a_row = (lane & 15), a_koff = (lane >> 4) * 8;
    const int b_row = (lane & 7),  b_koff = ((lane >> 3) & 1) * 8;

    for (int c = 0; c < 32; c++) {
        const int buf = c & 1;
        if (c < 31) asm volatile("cp.async.wait_group 1;" ::: "memory");
        else        asm volatile("cp.async.wait_group 0;" ::: "memory");
        __syncthreads();

        const uint32_t st = sbase + buf * OP_STAGE_B;
#pragma unroll
        for (int k16 = 0; k16 < 2; k16++) {
            uint32_t a[4][4], bf[4][2];
#pragma unroll
            for (int mi = 0; mi < 4; mi++)
                ldsm_x4(a[mi][0], a[mi][1], a[mi][2], a[mi][3],
                        st + ((wm * 64 + mi * 16 + a_row) * KSTRIDE + k16 * 16 + a_koff) * 2);
#pragma unroll
            for (int ni = 0; ni < 4; ni++)
                ldsm_x2(bf[ni][0], bf[ni][1],
                        st + G_TILE_B + ((wn * 32 + ni * 8 + b_row) * KSTRIDE + k16 * 16 + b_koff) * 2);
#pragma unroll
            for (int ni = 0; ni < 4; ni++)
#pragma unroll
                for (int mi = 0; mi < 4; mi++)
                    mma_f16(acc[mi][ni], a[mi], bf[ni][0], bf[ni][1]);
        }
        __syncthreads();
        if (c + 2 < 32) load_chunk(c + 2, buf);
    }

    const int gid = lane >> 2, tig = lane & 3;
#pragma unroll
    for (int mi = 0; mi < 4; mi++) {
#pragma unroll
        for (int half = 0; half < 2; half++) {
            const int m = m0 + wm * 64 + mi * 16 + gid + half * 8;
#pragma unroll
            for (int ni = 0; ni < 4; ni++) {
                const int n = n0 + wn * 32 + ni * 8 + tig * 2;
                *(float2*)&out_final[(size_t)m * D_MODEL + n] =
                    make_float2(acc[mi][ni][half * 2 + 0] + bo[n],
                                acc[mi][ni][half * 2 + 1] + bo[n + 1]);
            }
        }
    }
}

// ======================= fp16 flash attention, 2-way split-K, 2 CTAs/SM =======================
#define AT_KSTR 72
#define FQ_OFF  0
#define FK_OFF  18432
#define FV_OFF  (FK_OFF + 2 * 9216)
#define ATTN_SMEM4 (FV_OFF + 2 * 9216)   // 55296 B
#define SPLIT_TILES 16

__global__ __launch_bounds__(256, 2)
void attn_mma_kernel()
{
    extern __shared__ char smc[];
    const uint32_t base = smem_u32(smc);

    const int tid = threadIdx.x;
    const int wid = tid >> 5, lane = tid & 31;
    const int q0 = blockIdx.x * 128;
    const int h = blockIdx.y;
    const int bz = blockIdx.z >> 1, sp = blockIdx.z & 1;
    const int bh = bz * N_HEADS + h;
    const int T0 = sp * SPLIT_TILES;

    const int a_row = (lane & 15), a_koff = (lane >> 4) * 8;
    const int b_row4 = (lane & 7) + ((lane >> 4) << 3);
    const int b_koff4 = ((lane >> 3) & 1) * 8;
    const int t_row = (lane & 7) + (((lane >> 3) & 1) << 3);
    const int t_col8 = (lane >> 4) * 8;
    const int gid = lane >> 2, tig = lane & 3;

    // ---- load Q fragments ----
    uint32_t qf[4][4];
    {
#pragma unroll
        for (int it = 0; it < 4; it++) {
            int idx = tid + it * 256;
            int row = idx >> 3, cp = idx & 7;
            cp16(base + FQ_OFF + (row * AT_KSTR + cp * 8) * 2,
                 g_Qf + ((size_t)bh * S_LEN + q0 + row) * DK + cp * 8);
        }
        asm volatile("cp.async.commit_group;" ::: "memory");
        asm volatile("cp.async.wait_group 0;" ::: "memory");
        __syncthreads();
#pragma unroll
        for (int k16 = 0; k16 < 4; k16++)
            ldsm_x4(qf[k16][0], qf[k16][1], qf[k16][2], qf[k16][3],
                    base + FQ_OFF + ((wid * 16 + a_row) * AT_KSTR + k16 * 16 + a_koff) * 2);
        __syncthreads();
    }

    auto load_kv = [&](int T, int bufx) {
        const int t0 = T * 64;
#pragma unroll
        for (int hf = 0; hf < 2; hf++) {
            int rem = tid + hf * 256;
            int row = rem >> 3, cp = rem & 7;
            cp16(base + FK_OFF + bufx * 9216 + (row * AT_KSTR + cp * 8) * 2,
                 g_Kf + ((size_t)bh * S_LEN + t0 + row) * DK + cp * 8);
            cp16(base + FV_OFF + bufx * 9216 + (row * AT_KSTR + cp * 8) * 2,
                 g_Vf + ((size_t)bh * S_LEN + t0 + row) * DK + cp * 8);
        }
        asm volatile("cp.async.commit_group;" ::: "memory");
    };

    float oacc[8][4];
#pragma unroll
    for (int ni = 0; ni < 8; ni++)
#pragma unroll
        for (int c = 0; c < 4; c++) oacc[ni][c] = 0.f;
    float m0 = -1e30f, m1 = -1e30f, l0 = 0.f, l1 = 0.f;

    load_kv(T0, 0);

#pragma unroll 1
    for (int Ti = 0; Ti < SPLIT_TILES; Ti++) {
        const int buf = Ti & 1;
        asm volatile("cp.async.wait_group 0;" ::: "memory");
        __syncthreads();
        if (Ti + 1 < SPLIT_TILES) load_kv(T0 + Ti + 1, buf ^ 1);

        const uint32_t kb = base + FK_OFF + buf * 9216;
        const uint32_t vb = base + FV_OFF + buf * 9216;

        // ---- QK^T (fp16) ----
        float sacc[8][4];
#pragma unroll
        for (int ni = 0; ni < 8; ni++)
#pragma unroll
            for (int c = 0; c < 4; c++) sacc[ni][c] = 0.f;

#pragma unroll
        for (int kd = 0; kd < 4; kd++) {
            uint32_t kf[4][4];
#pragma unroll
            for (int np = 0; np < 4; np++)
                ldsm_x4(kf[np][0], kf[np][1], kf[np][2], kf[np][3],
                        kb + ((np * 16 + b_row4) * AT_KSTR + kd * 16 + b_koff4) * 2);
#pragma unroll
            for (int np = 0; np < 4; np++) {
                mma_f16(sacc[2 * np],     qf[kd], kf[np][0], kf[np][1]);
                mma_f16(sacc[2 * np + 1], qf[kd], kf[np][2], kf[np][3]);
            }
        }

        // ---- register softmax ----
        float mx0 = -1e30f, mx1 = -1e30f;
#pragma unroll
        for (int ni = 0; ni < 8; ni++) {
            mx0 = fmaxf(mx0, fmaxf(sacc[ni][0], sacc[ni][1]));
            mx1 = fmaxf(mx1, fmaxf(sacc[ni][2], sacc[ni][3]));
        }
        mx0 = fmaxf(mx0, __shfl_xor_sync(0xffffffffu, mx0, 1));
        mx0 = fmaxf(mx0, __shfl_xor_sync(0xffffffffu, mx0, 2));
        mx1 = fmaxf(mx1, __shfl_xor_sync(0xffffffffu, mx1, 1));
        mx1 = fmaxf(mx1, __shfl_xor_sync(0xffffffffu, mx1, 2));

        const float mn0 = fmaxf(m0, mx0), mn1 = fmaxf(m1, mx1);
        const float cr0 = __expf(m0 - mn0), cr1 = __expf(m1 - mn1);
        m0 = mn0; m1 = mn1;

        float s0 = 0.f, s1 = 0.f;
#pragma unroll
        for (int ni = 0; ni < 8; ni++) {
            sacc[ni][0] = __expf(sacc[ni][0] - mn0);
            sacc[ni][1] = __expf(sacc[ni][1] - mn0);
            sacc[ni][2] = __expf(sacc[ni][2] - mn1);
            sacc[ni][3] = __expf(sacc[ni][3] - mn1);
            s0 += sacc[ni][0] + sacc[ni][1];
            s1 += sacc[ni][2] + sacc[ni][3];
        }
        s0 += __shfl_xor_sync(0xffffffffu, s0, 1);
        s0 += __shfl_xor_sync(0xffffffffu, s0, 2);
        s1 += __shfl_xor_sync(0xffffffffu, s1, 1);
        s1 += __shfl_xor_sync(0xffffffffu, s1, 2);
        l0 = l0 * cr0 + s0;
        l1 = l1 * cr1 + s1;

#pragma unroll
        for (int ni = 0; ni < 8; ni++) {
            oacc[ni][0] *= cr0; oacc[ni][1] *= cr0;
            oacc[ni][2] *= cr1; oacc[ni][3] *= cr1;
        }

        // ---- P fragments ----
        uint32_t pf[4][4];
#pragma unroll
        for (int kt = 0; kt < 4; kt++) {
            const float* e0 = sacc[2 * kt];
            const float* e1 = sacc[2 * kt + 1];
            pf[kt][0] = pack_h2(e0[0], e0[1]);
            pf[kt][1] = pack_h2(e0[2], e0[3]);
            pf[kt][2] = pack_h2(e1[0], e1[1]);
            pf[kt][3] = pack_h2(e1[2], e1[3]);
        }

        // ---- PV (V row-major via ldmatrix.trans) ----
#pragma unroll
        for (int kt = 0; kt < 4; kt++) {
            uint32_t vf[4][4];
#pragma unroll
            for (int np = 0; np < 4; np++)
                ldsm_x4_t(vf[np][0], vf[np][1], vf[np][2], vf[np][3],
                          vb + ((kt * 16 + t_row) * AT_KSTR + np * 16 + t_col8) * 2);
#pragma unroll
            for (int np = 0; np < 4; np++) {
                mma_f16(oacc[2 * np],     pf[kt], vf[np][0], vf[np][1]);
                mma_f16(oacc[2 * np + 1], pf[kt], vf[np][2], vf[np][3]);
            }
        }
    }

    // ---- epilogue ----
#pragma unroll
    for (int hf = 0; hf < 2; hf++) {
        const int s = q0 + wid * 16 + gid + hf * 8;
        const size_t row = (size_t)bh * S_LEN + s;
#pragma unroll
        for (int ni = 0; ni < 8; ni++) {
            const int d = ni * 8 + tig * 2;
            *(float2*)&g_Opart[sp][row * DK + d] =
                make_float2(oacc[ni][hf * 2 + 0], oacc[ni][hf * 2 + 1]);
        }
        if (tig == 0)
            g_MLpart[sp][row] = make_float2(hf ? m1 : m0, hf ? l1 : l0);
    }
}

// combine the two split-K halves -> fp16 attention output
__global__ __launch_bounds__(256) void attn_combine_kernel()
{
    size_t idx = ((size_t)blockIdx.x * 256 + threadIdx.x) * 4;
    size_t r = idx >> 6;
    int d = (int)(idx & 63);
    float2 ml0 = g_MLpart[0][r], ml1 = g_MLpart[1][r];
    float m = fmaxf(ml0.x, ml1.x);
    float c0 = __expf(ml0.x - m), c1 = __expf(ml1.x - m);
    float inv = 1.f / (c0 * ml0.y + c1 * ml1.y);
    float4 o0 = *(float4*)&g_Opart[0][idx];
    float4 o1 = *(float4*)&g_Opart[1][idx];
    float v0 = (c0 * o0.x + c1 * o1.x) * inv;
    float v1 = (c0 * o0.y + c1 * o1.y) * inv;
    float v2 = (c0 * o0.z + c1 * o1.z) * inv;
    float v3 = (c0 * o0.w + c1 * o1.w) * inv;

    int bz = (int)(r / (N_HEADS * S_LEN));
    int h  = (int)((r / S_LEN) % N_HEADS);
    int s  = (int)(r % S_LEN);
    size_t o = ((size_t)bz * S_LEN + s) * D_MODEL + h * DK + d;

    *(__half2*)&g_Of[o]     = __floats2half2_rn(v0, v1);
    *(__half2*)&g_Of[o + 2] = __floats2half2_rn(v2, v3);
}

// =====================================================================
extern "C" void kernel_launch(void* const* d_in, const int* in_sizes, int n_in,
                              void* d_out, int out_size)
{
    const float* q   = (const float*)d_in[0];
    const float* k   = (const float*)d_in[1];
    const float* v   = (const float*)d_in[2];
    const float* kpe = (const float*)d_in[3];
    const float* Wq  = (const float*)d_in[4];
    const float* bq  = (const float*)d_in[5];
    const float* Wk  = (const float*)d_in[6];
    const float* bk  = (const float*)d_in[7];
    const float* Wv  = (const float*)d_in[8];
    const float* bv  = (const float*)d_in[9];
    const float* Wo  = (const float*)d_in[10];
    const float* bo  = (const float*)d_in[11];
    float* out = (float*)d_out;

    cudaFuncSetAttribute(attn_mma_kernel, cudaFuncAttributeMaxDynamicSharedMemorySize,
                         ATTN_SMEM4);
    cudaFuncSetAttribute(gemm_f16_kernel, cudaFuncAttributeMaxDynamicSharedMemorySize,
                         GEMM_SMEM);

    // prep
    dim3 gs(M_ROWS * D_MODEL / 1024, 3);
    cvt_qkv_kernel<<<gs, 256>>>(q, k, v);
    dim3 gw(32, 32, 4);
    splitW_kernel<<<gw, dim3(32, 8)>>>(Wq, Wk, Wv, Wo);

    // Q/K/V projections (fp16 2-pass)
    dim3 gp(D_MODEL / BN, M_ROWS / BM, 3);
    gemm_f16_kernel<<<gp, 256, GEMM_SMEM>>>(kpe, bq, bk, bv);

    // attention (fp16 tensor cores, 2 CTAs/SM, 2-way split-K)
    dim3 ga(S_LEN / 128, N_HEADS, B_SIZE * 2);
    attn_mma_kernel<<<ga, 256, ATTN_SMEM4>>>();
    attn_combine_kernel<<<BHS * DK / 1024, 256>>>();

    // output projection (fp16 single pass)
    dim3 go(D_MODEL / BN, M_ROWS / BM, 1);
    outproj_f16_kernel<<<go, 256>>>(bo, out);
}